// round 2
// baseline (speedup 1.0000x reference)
#include <cuda_runtime.h>
#include <cuda_bf16.h>
#include <math.h>

// Problem constants
#define BB 128
#define LC 256
#define LE 1024
#define DD 256
#define MM 512
#define NEGV (-1e9f)

// ---------------- scratch (single device global; aliased regions) ----------------
// Layout (floats):
//   [0]                 c      B*LC*D  (32MB)  -> later reused as att_c
//   [OFF_E]             e      B*LE*D  (128MB) -> later reused as beta
//   [OFF_ALIGN]         align  B*LC*LE (128MB) -> alpha written in-place
//   [OFF_ATTE]          att_e  B*LE*D  (128MB)
//   [OFF_R]             r1, r2 (2 * B*D)
#define OFF_C     ((size_t)0)
#define OFF_E     ((size_t)BB * LC * DD)
#define OFF_ALIGN (OFF_E + (size_t)BB * LE * DD)
#define OFF_ATTE  (OFF_ALIGN + (size_t)BB * LC * LE)
#define OFF_R1    (OFF_ATTE + (size_t)BB * LE * DD)
#define OFF_R2    (OFF_R1 + (size_t)BB * DD)
#define SCRATCH_FLOATS (OFF_R2 + (size_t)BB * DD)

__device__ float g_scratch[SCRATCH_FLOATS];   // ~416 MB total

// ---------------- generic tiled GEMMs: BM=BN=64, BK=16, 256 thr, 4x4/thr ----------------

// C = [relu](A @ B + bias), A row-major (M,K), B row-major (K,N). Batched via strides.
__global__ __launch_bounds__(256) void gemm_nn(
    const float* __restrict__ A, const float* __restrict__ B,
    const float* __restrict__ bias, float* __restrict__ C,
    int N, int K, size_t sA, size_t sB, size_t sC, int doRelu)
{
    __shared__ float As[16][64];
    __shared__ float Bs[16][64];
    const int tid = threadIdx.x;
    const int tx = tid & 15, ty = tid >> 4;
    const int m0 = blockIdx.y * 64, n0 = blockIdx.x * 64;
    A += (size_t)blockIdx.z * sA;
    B += (size_t)blockIdx.z * sB;
    C += (size_t)blockIdx.z * sC;

    float acc[4][4] = {};
    for (int k0 = 0; k0 < K; k0 += 16) {
#pragma unroll
        for (int i = 0; i < 4; i++) {
            int idx = tid + i * 256;
            int m = idx >> 4, k = idx & 15;
            As[k][m] = A[(size_t)(m0 + m) * K + k0 + k];
        }
#pragma unroll
        for (int i = 0; i < 4; i++) {
            int idx = tid + i * 256;
            int k = idx >> 6, n = idx & 63;
            Bs[k][n] = B[(size_t)(k0 + k) * N + n0 + n];
        }
        __syncthreads();
#pragma unroll
        for (int kk = 0; kk < 16; kk++) {
            float ar[4], br_[4];
#pragma unroll
            for (int i = 0; i < 4; i++) ar[i] = As[kk][ty * 4 + i];
#pragma unroll
            for (int j = 0; j < 4; j++) br_[j] = Bs[kk][tx * 4 + j];
#pragma unroll
            for (int i = 0; i < 4; i++)
#pragma unroll
                for (int j = 0; j < 4; j++) acc[i][j] = fmaf(ar[i], br_[j], acc[i][j]);
        }
        __syncthreads();
    }
#pragma unroll
    for (int i = 0; i < 4; i++)
#pragma unroll
        for (int j = 0; j < 4; j++) {
            float v = acc[i][j];
            if (bias) v += bias[n0 + tx * 4 + j];
            if (doRelu) v = fmaxf(v, 0.0f);
            C[(size_t)(m0 + ty * 4 + i) * N + n0 + tx * 4 + j] = v;
        }
}

// C = A @ B^T. A (M,K) row-major, B (N,K) row-major. Batched.
__global__ __launch_bounds__(256) void gemm_nt(
    const float* __restrict__ A, const float* __restrict__ B, float* __restrict__ C,
    int N, int K, size_t sA, size_t sB, size_t sC)
{
    __shared__ float As[16][64];
    __shared__ float Bs[16][64];
    const int tid = threadIdx.x;
    const int tx = tid & 15, ty = tid >> 4;
    const int m0 = blockIdx.y * 64, n0 = blockIdx.x * 64;
    A += (size_t)blockIdx.z * sA;
    B += (size_t)blockIdx.z * sB;
    C += (size_t)blockIdx.z * sC;

    float acc[4][4] = {};
    for (int k0 = 0; k0 < K; k0 += 16) {
#pragma unroll
        for (int i = 0; i < 4; i++) {
            int idx = tid + i * 256;
            int m = idx >> 4, k = idx & 15;
            As[k][m] = A[(size_t)(m0 + m) * K + k0 + k];
        }
#pragma unroll
        for (int i = 0; i < 4; i++) {
            int idx = tid + i * 256;
            int n = idx >> 4, k = idx & 15;
            Bs[k][n] = B[(size_t)(n0 + n) * K + k0 + k];
        }
        __syncthreads();
#pragma unroll
        for (int kk = 0; kk < 16; kk++) {
            float ar[4], br_[4];
#pragma unroll
            for (int i = 0; i < 4; i++) ar[i] = As[kk][ty * 4 + i];
#pragma unroll
            for (int j = 0; j < 4; j++) br_[j] = Bs[kk][tx * 4 + j];
#pragma unroll
            for (int i = 0; i < 4; i++)
#pragma unroll
                for (int j = 0; j < 4; j++) acc[i][j] = fmaf(ar[i], br_[j], acc[i][j]);
        }
        __syncthreads();
    }
#pragma unroll
    for (int i = 0; i < 4; i++)
#pragma unroll
        for (int j = 0; j < 4; j++)
            C[(size_t)(m0 + ty * 4 + i) * N + n0 + tx * 4 + j] = acc[i][j];
}

// C = A^T @ B. A stored (K, lda) row-major, B (K,N) row-major. Batched.
__global__ __launch_bounds__(256) void gemm_tn(
    const float* __restrict__ A, const float* __restrict__ B, float* __restrict__ C,
    int N, int K, int lda, size_t sA, size_t sB, size_t sC)
{
    __shared__ float As[16][64];
    __shared__ float Bs[16][64];
    const int tid = threadIdx.x;
    const int tx = tid & 15, ty = tid >> 4;
    const int m0 = blockIdx.y * 64, n0 = blockIdx.x * 64;
    A += (size_t)blockIdx.z * sA;
    B += (size_t)blockIdx.z * sB;
    C += (size_t)blockIdx.z * sC;

    float acc[4][4] = {};
    for (int k0 = 0; k0 < K; k0 += 16) {
#pragma unroll
        for (int i = 0; i < 4; i++) {
            int idx = tid + i * 256;
            int k = idx >> 6, m = idx & 63;
            As[k][m] = A[(size_t)(k0 + k) * lda + m0 + m];
        }
#pragma unroll
        for (int i = 0; i < 4; i++) {
            int idx = tid + i * 256;
            int k = idx >> 6, n = idx & 63;
            Bs[k][n] = B[(size_t)(k0 + k) * N + n0 + n];
        }
        __syncthreads();
#pragma unroll
        for (int kk = 0; kk < 16; kk++) {
            float ar[4], br_[4];
#pragma unroll
            for (int i = 0; i < 4; i++) ar[i] = As[kk][ty * 4 + i];
#pragma unroll
            for (int j = 0; j < 4; j++) br_[j] = Bs[kk][tx * 4 + j];
#pragma unroll
            for (int i = 0; i < 4; i++)
#pragma unroll
                for (int j = 0; j < 4; j++) acc[i][j] = fmaf(ar[i], br_[j], acc[i][j]);
        }
        __syncthreads();
    }
#pragma unroll
    for (int i = 0; i < 4; i++)
#pragma unroll
        for (int j = 0; j < 4; j++)
            C[(size_t)(m0 + ty * 4 + i) * N + n0 + tx * 4 + j] = acc[i][j];
}

// ---------------- softmax kernels ----------------

// beta = softmax over Lc (column-wise), masked by criteria_mask.
// Reads align, writes beta. grid (LE/32, B), block (32,8)
__global__ void beta_kernel(const float* __restrict__ align_, float* __restrict__ beta,
                            const int* __restrict__ cmask)
{
    const int b = blockIdx.y;
    const int e = blockIdx.x * 32 + threadIdx.x;
    const int tx = threadIdx.x, ty = threadIdx.y;
    const float* base = align_ + (size_t)b * LC * LE + e;
    float* outb = beta + (size_t)b * LC * LE + e;

    float vals[LC / 8];
    float mx = -INFINITY;
#pragma unroll
    for (int i = 0; i < LC / 8; i++) {
        int l = ty + i * 8;
        float v = base[(size_t)l * LE] + (1.0f - (float)cmask[b * LC + l]) * NEGV;
        vals[i] = v;
        mx = fmaxf(mx, v);
    }
    __shared__ float red[8][32];
    red[ty][tx] = mx;
    __syncthreads();
    if (ty == 0) {
        float m2 = red[0][tx];
#pragma unroll
        for (int i = 1; i < 8; i++) m2 = fmaxf(m2, red[i][tx]);
        red[0][tx] = m2;
    }
    __syncthreads();
    mx = red[0][tx];
    __syncthreads();

    float s = 0.0f;
#pragma unroll
    for (int i = 0; i < LC / 8; i++) {
        vals[i] = expf(vals[i] - mx);
        s += vals[i];
    }
    red[ty][tx] = s;
    __syncthreads();
    if (ty == 0) {
        float s2 = 0.0f;
#pragma unroll
        for (int i = 0; i < 8; i++) s2 += red[i][tx];
        red[0][tx] = s2;
    }
    __syncthreads();
    float inv = 1.0f / red[0][tx];
#pragma unroll
    for (int i = 0; i < LC / 8; i++) {
        int l = ty + i * 8;
        outb[(size_t)l * LE] = vals[i] * inv;
    }
}

// alpha = softmax over Le (row-wise), masked by ehr_mask. In-place.
// grid (LC, B), block 256
__global__ void alpha_kernel(float* __restrict__ align_, const int* __restrict__ emask)
{
    const int b = blockIdx.y;
    const int l = blockIdx.x;
    const int t = threadIdx.x;
    float* row = align_ + ((size_t)b * LC + l) * LE;

    float v[4];
    float mx = -INFINITY;
#pragma unroll
    for (int j = 0; j < 4; j++) {
        int e = t + j * 256;
        v[j] = row[e] + (1.0f - (float)emask[b * LE + e]) * NEGV;
        mx = fmaxf(mx, v[j]);
    }
    __shared__ float sm[256];
    sm[t] = mx;
    __syncthreads();
    for (int s = 128; s > 0; s >>= 1) {
        if (t < s) sm[t] = fmaxf(sm[t], sm[t + s]);
        __syncthreads();
    }
    mx = sm[0];
    __syncthreads();

    float sum = 0.0f;
#pragma unroll
    for (int j = 0; j < 4; j++) {
        v[j] = expf(v[j] - mx);
        sum += v[j];
    }
    sm[t] = sum;
    __syncthreads();
    for (int s = 128; s > 0; s >>= 1) {
        if (t < s) sm[t] += sm[t + s];
        __syncthreads();
    }
    float inv = 1.0f / sm[0];
#pragma unroll
    for (int j = 0; j < 4; j++) row[t + j * 256] = v[j] * inv;
}

// ---------------- fused concat GEMM + relu + row-sum ----------------
// r[b,n] += sum_m relu( [X1|X2][m,:] @ Wr + br )[n]   (K = 2D = 512, N = D)
// grid (D/64, L/64, B), block 256
__global__ __launch_bounds__(256) void gemm_concat_relu_rowsum(
    const float* __restrict__ X1, const float* __restrict__ X2,
    const float* __restrict__ Wr, const float* __restrict__ br,
    float* __restrict__ r, int L)
{
    __shared__ float As[16][64];
    __shared__ float Bs[16][64];
    __shared__ float red[16][64];
    const int tid = threadIdx.x;
    const int tx = tid & 15, ty = tid >> 4;
    const int b = blockIdx.z;
    const int m0 = blockIdx.y * 64, n0 = blockIdx.x * 64;
    const float* A1 = X1 + (size_t)b * L * DD;
    const float* A2 = X2 + (size_t)b * L * DD;

    float acc[4][4] = {};
    for (int k0 = 0; k0 < 2 * DD; k0 += 16) {
#pragma unroll
        for (int i = 0; i < 4; i++) {
            int idx = tid + i * 256;
            int m = idx >> 4, k = idx & 15;
            int kk = k0 + k;
            As[k][m] = (kk < DD) ? A1[(size_t)(m0 + m) * DD + kk]
                                 : A2[(size_t)(m0 + m) * DD + kk - DD];
        }
#pragma unroll
        for (int i = 0; i < 4; i++) {
            int idx = tid + i * 256;
            int k = idx >> 6, n = idx & 63;
            Bs[k][n] = Wr[(size_t)(k0 + k) * DD + n0 + n];
        }
        __syncthreads();
#pragma unroll
        for (int kk = 0; kk < 16; kk++) {
            float ar[4], br_[4];
#pragma unroll
            for (int i = 0; i < 4; i++) ar[i] = As[kk][ty * 4 + i];
#pragma unroll
            for (int j = 0; j < 4; j++) br_[j] = Bs[kk][tx * 4 + j];
#pragma unroll
            for (int i = 0; i < 4; i++)
#pragma unroll
                for (int j = 0; j < 4; j++) acc[i][j] = fmaf(ar[i], br_[j], acc[i][j]);
        }
        __syncthreads();
    }
    // epilogue: relu + partial row sum
#pragma unroll
    for (int j = 0; j < 4; j++) {
        float bias = br[n0 + tx * 4 + j];
        float p = 0.0f;
#pragma unroll
        for (int i = 0; i < 4; i++) p += fmaxf(acc[i][j] + bias, 0.0f);
        red[ty][tx * 4 + j] = p;
    }
    __syncthreads();
    if (tid < 64) {
        float s = 0.0f;
#pragma unroll
        for (int t = 0; t < 16; t++) s += red[t][tid];
        atomicAdd(&r[(size_t)b * DD + n0 + tid], s);
    }
}

// ---------------- final head ----------------
// m = [r1, r2, r1*r2, r1-r2] (1024); h = relu(m@Wm+bm) (512); out = h@Wo+bo (3)
// grid (B), block 512
__global__ void head_kernel(const float* __restrict__ r1, const float* __restrict__ r2,
                            const float* __restrict__ Wm, const float* __restrict__ bm,
                            const float* __restrict__ Wo, const float* __restrict__ bo,
                            float* __restrict__ out)
{
    const int b = blockIdx.x;
    const int t = threadIdx.x;
    __shared__ float mv[4 * DD];
    __shared__ float outacc[3];
    if (t < DD) {
        float a = r1[(size_t)b * DD + t];
        float c = r2[(size_t)b * DD + t];
        mv[t] = a;
        mv[DD + t] = c;
        mv[2 * DD + t] = a * c;
        mv[3 * DD + t] = a - c;
    }
    if (t < 3) outacc[t] = 0.0f;
    __syncthreads();

    float acc = bm[t];
#pragma unroll 8
    for (int k = 0; k < 4 * DD; k++) acc = fmaf(mv[k], Wm[(size_t)k * MM + t], acc);
    float h = fmaxf(acc, 0.0f);

#pragma unroll
    for (int i = 0; i < 3; i++) atomicAdd(&outacc[i], h * Wo[(size_t)t * 3 + i]);
    __syncthreads();
    if (t < 3) out[(size_t)b * 3 + t] = outacc[t] + bo[t];
}

// ---------------- launch ----------------
extern "C" void kernel_launch(void* const* d_in, const int* in_sizes, int n_in,
                              void* d_out, int out_size)
{
    const float* criteria = (const float*)d_in[0];
    const float* ehr      = (const float*)d_in[1];
    const int*   cmask    = (const int*)d_in[2];
    const int*   emask    = (const int*)d_in[3];
    const float* Wa       = (const float*)d_in[4];
    const float* ba       = (const float*)d_in[5];
    const float* Wr       = (const float*)d_in[6];
    const float* br       = (const float*)d_in[7];
    const float* Wm       = (const float*)d_in[8];
    const float* bm       = (const float*)d_in[9];
    const float* Wo       = (const float*)d_in[10];
    const float* bo       = (const float*)d_in[11];
    float* out = (float*)d_out;

    float* base;
    cudaGetSymbolAddress((void**)&base, g_scratch);
    float* p_c     = base + OFF_C;
    float* p_e     = base + OFF_E;
    float* p_align = base + OFF_ALIGN;
    float* p_beta  = base + OFF_E;     // alias: e dead after align GEMM
    float* p_attc  = base + OFF_C;     // alias: c dead after align GEMM
    float* p_atte  = base + OFF_ATTE;
    float* p_r1    = base + OFF_R1;
    float* p_r2    = base + OFF_R2;

    // 1) c = relu(criteria @ Wa + ba)   (flat GEMM over B*LC rows)
    gemm_nn<<<dim3(DD / 64, (BB * LC) / 64, 1), 256>>>(
        criteria, Wa, ba, p_c, DD, DD, 0, 0, 0, 1);
    // 2) e = relu(ehr @ Wa + ba)
    gemm_nn<<<dim3(DD / 64, (BB * LE) / 64, 1), 256>>>(
        ehr, Wa, ba, p_e, DD, DD, 0, 0, 0, 1);
    // 3) align = c @ e^T  (batched NT)
    gemm_nt<<<dim3(LE / 64, LC / 64, BB), 256>>>(
        p_c, p_e, p_align, LE, DD,
        (size_t)LC * DD, (size_t)LE * DD, (size_t)LC * LE);
    // 4) beta (softmax over Lc, masked by criteria_mask) -> aliases e
    beta_kernel<<<dim3(LE / 32, BB), dim3(32, 8)>>>(p_align, p_beta, cmask);
    // 5) alpha in-place (softmax over Le, masked by ehr_mask)
    alpha_kernel<<<dim3(LC, BB), 256>>>(p_align, emask);
    // 6) att_c = alpha @ ehr   (batched NN, K=LE) -> aliases c
    gemm_nn<<<dim3(DD / 64, LC / 64, BB), 256>>>(
        p_align, ehr, nullptr, p_attc, DD, LE,
        (size_t)LC * LE, (size_t)LE * DD, (size_t)LC * DD, 0);
    // 7) att_e = beta^T @ criteria  (batched TN, K=LC, lda=LE)
    gemm_tn<<<dim3(DD / 64, LE / 64, BB), 256>>>(
        p_beta, criteria, p_atte, DD, LC, LE,
        (size_t)LC * LE, (size_t)LC * DD, (size_t)LE * DD);
    // 8) r1, r2
    cudaMemsetAsync(p_r1, 0, (size_t)2 * BB * DD * sizeof(float));
    gemm_concat_relu_rowsum<<<dim3(DD / 64, LC / 64, BB), 256>>>(
        p_attc, criteria, Wr, br, p_r1, LC);
    gemm_concat_relu_rowsum<<<dim3(DD / 64, LE / 64, BB), 256>>>(
        p_atte, ehr, Wr, br, p_r2, LE);
    // 9) head
    head_kernel<<<BB, MM>>>(p_r1, p_r2, Wm, bm, Wo, bo, out);
}

// round 3
// speedup vs baseline: 1.8478x; 1.8478x over previous
#include <cuda_runtime.h>
#include <cuda_bf16.h>
#include <math.h>
#include <stdint.h>

// Problem constants
#define BB 128
#define LC 256
#define LE 1024
#define DD 256
#define MM 512
#define NEGV (-1e9f)

// GEMM tile config
#define BM 128
#define BN 64
#define BK 16
#define PA (BM + 4)
#define PB (BN + 4)

// ---------------- scratch (single device global; aliased regions) ----------------
#define OFF_C     ((size_t)0)
#define OFF_E     ((size_t)BB * LC * DD)
#define OFF_ALIGN (OFF_E + (size_t)BB * LE * DD)
#define OFF_ATTE  (OFF_ALIGN + (size_t)BB * LC * LE)
#define OFF_R1    (OFF_ATTE + (size_t)BB * LE * DD)
#define OFF_R2    (OFF_R1 + (size_t)BB * DD)
#define SCRATCH_FLOATS (OFF_R2 + (size_t)BB * DD)

__device__ float g_scratch[SCRATCH_FLOATS];   // ~416 MB total

// ---------------- tf32 helpers ----------------
__device__ __forceinline__ uint32_t f2tf32(float x) {
    uint32_t r;
    asm("cvt.rna.tf32.f32 %0, %1;" : "=r"(r) : "f"(x));
    return r;
}

// D = A(16x8) * B(8x8) + C, tf32 inputs, f32 accum. row.col layout.
__device__ __forceinline__ void mma_tf32(float* c, const uint32_t* a, const uint32_t* b) {
    asm volatile(
        "mma.sync.aligned.m16n8k8.row.col.f32.tf32.tf32.f32 "
        "{%0,%1,%2,%3}, {%4,%5,%6,%7}, {%8,%9}, {%0,%1,%2,%3};"
        : "+f"(c[0]), "+f"(c[1]), "+f"(c[2]), "+f"(c[3])
        : "r"(a[0]), "r"(a[1]), "r"(a[2]), "r"(a[3]), "r"(b[0]), "r"(b[1]));
}

// Shared inner compute: As[BK][PA] (tf32 bits, [k][m]), Bs[BK][PB] ([k][n]).
// Warp layout: wm = (wid&3)*32, wn = (wid>>2)*32. acc[2][4][4].
__device__ __forceinline__ void mma_tile_compute(
    const uint32_t (*As)[PA], const uint32_t (*Bs)[PB],
    int lane, int wm, int wn, float acc[2][4][4])
{
    const int c4 = lane & 3;
    const int g8 = lane >> 2;
#pragma unroll
    for (int ks = 0; ks < BK; ks += 8) {
        uint32_t af[2][4];
#pragma unroll
        for (int mi = 0; mi < 2; mi++) {
            int mrow = wm + mi * 16 + g8;
            af[mi][0] = As[ks + c4][mrow];
            af[mi][1] = As[ks + c4][mrow + 8];
            af[mi][2] = As[ks + c4 + 4][mrow];
            af[mi][3] = As[ks + c4 + 4][mrow + 8];
        }
        uint32_t bf[4][2];
#pragma unroll
        for (int ni = 0; ni < 4; ni++) {
            int ncol = wn + ni * 8 + g8;
            bf[ni][0] = Bs[ks + c4][ncol];
            bf[ni][1] = Bs[ks + c4 + 4][ncol];
        }
#pragma unroll
        for (int mi = 0; mi < 2; mi++)
#pragma unroll
            for (int ni = 0; ni < 4; ni++)
                mma_tf32(acc[mi][ni], af[mi], bf[ni]);
    }
}

// ---------------- GEMM kernels (tensor-core tf32) ----------------

// C = [relu](A @ B + bias). A (M,K) rm, B (K,N) rm. Batched by strides.
__global__ __launch_bounds__(256) void mm_nn(
    const float* __restrict__ A, const float* __restrict__ B,
    const float* __restrict__ bias, float* __restrict__ C,
    int N, int K, size_t sA, size_t sB, size_t sC, int doRelu)
{
    __shared__ uint32_t As[BK][PA];
    __shared__ uint32_t Bs[BK][PB];
    const int tid = threadIdx.x;
    const int lane = tid & 31, wid = tid >> 5;
    const int wm = (wid & 3) * 32, wn = (wid >> 2) * 32;
    const int m0 = blockIdx.y * BM, n0 = blockIdx.x * BN;
    A += (size_t)blockIdx.z * sA;
    B += (size_t)blockIdx.z * sB;
    C += (size_t)blockIdx.z * sC;

    float acc[2][4][4] = {};
    for (int k0 = 0; k0 < K; k0 += BK) {
#pragma unroll
        for (int i = 0; i < (BM * BK) / 256; i++) {
            int idx = tid + i * 256;
            int m = idx >> 4, k = idx & 15;
            As[k][m] = f2tf32(A[(size_t)(m0 + m) * K + k0 + k]);
        }
#pragma unroll
        for (int i = 0; i < (BN * BK) / 256; i++) {
            int idx = tid + i * 256;
            int n = idx & 63, k = idx >> 6;
            Bs[k][n] = f2tf32(B[(size_t)(k0 + k) * N + n0 + n]);
        }
        __syncthreads();
        mma_tile_compute(As, Bs, lane, wm, wn, acc);
        __syncthreads();
    }
#pragma unroll
    for (int mi = 0; mi < 2; mi++)
#pragma unroll
        for (int ni = 0; ni < 4; ni++) {
            int row = m0 + wm + mi * 16 + (lane >> 2);
            int col = n0 + wn + ni * 8 + 2 * (lane & 3);
            float v0 = acc[mi][ni][0], v1 = acc[mi][ni][1];
            float v2 = acc[mi][ni][2], v3 = acc[mi][ni][3];
            if (bias) { v0 += bias[col]; v1 += bias[col + 1]; v2 += bias[col]; v3 += bias[col + 1]; }
            if (doRelu) {
                v0 = fmaxf(v0, 0.f); v1 = fmaxf(v1, 0.f);
                v2 = fmaxf(v2, 0.f); v3 = fmaxf(v3, 0.f);
            }
            *(float2*)&C[(size_t)row * N + col] = make_float2(v0, v1);
            *(float2*)&C[(size_t)(row + 8) * N + col] = make_float2(v2, v3);
        }
}

// C = A @ B^T. A (M,K) rm, B (N,K) rm. Batched.
__global__ __launch_bounds__(256) void mm_nt(
    const float* __restrict__ A, const float* __restrict__ B, float* __restrict__ C,
    int N, int K, size_t sA, size_t sB, size_t sC)
{
    __shared__ uint32_t As[BK][PA];
    __shared__ uint32_t Bs[BK][PB];
    const int tid = threadIdx.x;
    const int lane = tid & 31, wid = tid >> 5;
    const int wm = (wid & 3) * 32, wn = (wid >> 2) * 32;
    const int m0 = blockIdx.y * BM, n0 = blockIdx.x * BN;
    A += (size_t)blockIdx.z * sA;
    B += (size_t)blockIdx.z * sB;
    C += (size_t)blockIdx.z * sC;

    float acc[2][4][4] = {};
    for (int k0 = 0; k0 < K; k0 += BK) {
#pragma unroll
        for (int i = 0; i < (BM * BK) / 256; i++) {
            int idx = tid + i * 256;
            int m = idx >> 4, k = idx & 15;
            As[k][m] = f2tf32(A[(size_t)(m0 + m) * K + k0 + k]);
        }
#pragma unroll
        for (int i = 0; i < (BN * BK) / 256; i++) {
            int idx = tid + i * 256;
            int n = idx >> 4, k = idx & 15;
            Bs[k][n] = f2tf32(B[(size_t)(n0 + n) * K + k0 + k]);
        }
        __syncthreads();
        mma_tile_compute(As, Bs, lane, wm, wn, acc);
        __syncthreads();
    }
#pragma unroll
    for (int mi = 0; mi < 2; mi++)
#pragma unroll
        for (int ni = 0; ni < 4; ni++) {
            int row = m0 + wm + mi * 16 + (lane >> 2);
            int col = n0 + wn + ni * 8 + 2 * (lane & 3);
            *(float2*)&C[(size_t)row * N + col] = make_float2(acc[mi][ni][0], acc[mi][ni][1]);
            *(float2*)&C[(size_t)(row + 8) * N + col] = make_float2(acc[mi][ni][2], acc[mi][ni][3]);
        }
}

// C = A^T @ B. A stored (K, lda) rm, B (K,N) rm. Batched.
__global__ __launch_bounds__(256) void mm_tn(
    const float* __restrict__ A, const float* __restrict__ B, float* __restrict__ C,
    int N, int K, int lda, size_t sA, size_t sB, size_t sC)
{
    __shared__ uint32_t As[BK][PA];
    __shared__ uint32_t Bs[BK][PB];
    const int tid = threadIdx.x;
    const int lane = tid & 31, wid = tid >> 5;
    const int wm = (wid & 3) * 32, wn = (wid >> 2) * 32;
    const int m0 = blockIdx.y * BM, n0 = blockIdx.x * BN;
    A += (size_t)blockIdx.z * sA;
    B += (size_t)blockIdx.z * sB;
    C += (size_t)blockIdx.z * sC;

    float acc[2][4][4] = {};
    for (int k0 = 0; k0 < K; k0 += BK) {
#pragma unroll
        for (int i = 0; i < (BM * BK) / 256; i++) {
            int idx = tid + i * 256;
            int m = idx & 127, k = idx >> 7;
            As[k][m] = f2tf32(A[(size_t)(k0 + k) * lda + m0 + m]);
        }
#pragma unroll
        for (int i = 0; i < (BN * BK) / 256; i++) {
            int idx = tid + i * 256;
            int n = idx & 63, k = idx >> 6;
            Bs[k][n] = f2tf32(B[(size_t)(k0 + k) * N + n0 + n]);
        }
        __syncthreads();
        mma_tile_compute(As, Bs, lane, wm, wn, acc);
        __syncthreads();
    }
#pragma unroll
    for (int mi = 0; mi < 2; mi++)
#pragma unroll
        for (int ni = 0; ni < 4; ni++) {
            int row = m0 + wm + mi * 16 + (lane >> 2);
            int col = n0 + wn + ni * 8 + 2 * (lane & 3);
            *(float2*)&C[(size_t)row * N + col] = make_float2(acc[mi][ni][0], acc[mi][ni][1]);
            *(float2*)&C[(size_t)(row + 8) * N + col] = make_float2(acc[mi][ni][2], acc[mi][ni][3]);
        }
}

// r[b,n] += sum_m relu( [X1|X2][m,:] @ Wr + br )[n]   (K = 2D, N = D)
__global__ __launch_bounds__(256) void mm_concat_relu_rowsum(
    const float* __restrict__ X1, const float* __restrict__ X2,
    const float* __restrict__ Wr, const float* __restrict__ br,
    float* __restrict__ r, int L)
{
    __shared__ uint32_t As[BK][PA];
    __shared__ uint32_t Bs[BK][PB];
    __shared__ float colsum[BN];
    const int tid = threadIdx.x;
    const int lane = tid & 31, wid = tid >> 5;
    const int wm = (wid & 3) * 32, wn = (wid >> 2) * 32;
    const int b = blockIdx.z;
    const int m0 = blockIdx.y * BM, n0 = blockIdx.x * BN;
    const float* A1 = X1 + (size_t)b * L * DD;
    const float* A2 = X2 + (size_t)b * L * DD;

    if (tid < BN) colsum[tid] = 0.0f;

    float acc[2][4][4] = {};
    for (int k0 = 0; k0 < 2 * DD; k0 += BK) {
#pragma unroll
        for (int i = 0; i < (BM * BK) / 256; i++) {
            int idx = tid + i * 256;
            int m = idx >> 4;
            int kk = k0 + (idx & 15);
            float v = (kk < DD) ? A1[(size_t)(m0 + m) * DD + kk]
                                : A2[(size_t)(m0 + m) * DD + kk - DD];
            As[idx & 15][m] = f2tf32(v);
        }
#pragma unroll
        for (int i = 0; i < (BN * BK) / 256; i++) {
            int idx = tid + i * 256;
            int n = idx & 63, k = idx >> 6;
            Bs[k][n] = f2tf32(Wr[(size_t)(k0 + k) * DD + n0 + n]);
        }
        __syncthreads();
        mma_tile_compute(As, Bs, lane, wm, wn, acc);
        __syncthreads();
    }
    // epilogue: relu(acc + bias), partial column sums
#pragma unroll
    for (int ni = 0; ni < 4; ni++) {
        int col = wn + ni * 8 + 2 * (lane & 3);
        float b0 = br[n0 + col], b1 = br[n0 + col + 1];
        float s0 = 0.f, s1 = 0.f;
#pragma unroll
        for (int mi = 0; mi < 2; mi++) {
            s0 += fmaxf(acc[mi][ni][0] + b0, 0.f) + fmaxf(acc[mi][ni][2] + b0, 0.f);
            s1 += fmaxf(acc[mi][ni][1] + b1, 0.f) + fmaxf(acc[mi][ni][3] + b1, 0.f);
        }
        atomicAdd(&colsum[col], s0);
        atomicAdd(&colsum[col + 1], s1);
    }
    __syncthreads();
    if (tid < BN) atomicAdd(&r[(size_t)b * DD + n0 + tid], colsum[tid]);
}

// ---------------- softmax kernels (unchanged from R2) ----------------

__global__ void beta_kernel(const float* __restrict__ align_, float* __restrict__ beta,
                            const int* __restrict__ cmask)
{
    const int b = blockIdx.y;
    const int e = blockIdx.x * 32 + threadIdx.x;
    const int tx = threadIdx.x, ty = threadIdx.y;
    const float* base = align_ + (size_t)b * LC * LE + e;
    float* outb = beta + (size_t)b * LC * LE + e;

    float vals[LC / 8];
    float mx = -INFINITY;
#pragma unroll
    for (int i = 0; i < LC / 8; i++) {
        int l = ty + i * 8;
        float v = base[(size_t)l * LE] + (1.0f - (float)cmask[b * LC + l]) * NEGV;
        vals[i] = v;
        mx = fmaxf(mx, v);
    }
    __shared__ float red[8][32];
    red[ty][tx] = mx;
    __syncthreads();
    if (ty == 0) {
        float m2 = red[0][tx];
#pragma unroll
        for (int i = 1; i < 8; i++) m2 = fmaxf(m2, red[i][tx]);
        red[0][tx] = m2;
    }
    __syncthreads();
    mx = red[0][tx];
    __syncthreads();

    float s = 0.0f;
#pragma unroll
    for (int i = 0; i < LC / 8; i++) {
        vals[i] = expf(vals[i] - mx);
        s += vals[i];
    }
    red[ty][tx] = s;
    __syncthreads();
    if (ty == 0) {
        float s2 = 0.0f;
#pragma unroll
        for (int i = 0; i < 8; i++) s2 += red[i][tx];
        red[0][tx] = s2;
    }
    __syncthreads();
    float inv = 1.0f / red[0][tx];
#pragma unroll
    for (int i = 0; i < LC / 8; i++) {
        int l = ty + i * 8;
        outb[(size_t)l * LE] = vals[i] * inv;
    }
}

__global__ void alpha_kernel(float* __restrict__ align_, const int* __restrict__ emask)
{
    const int b = blockIdx.y;
    const int l = blockIdx.x;
    const int t = threadIdx.x;
    float* row = align_ + ((size_t)b * LC + l) * LE;

    float v[4];
    float mx = -INFINITY;
#pragma unroll
    for (int j = 0; j < 4; j++) {
        int e = t + j * 256;
        v[j] = row[e] + (1.0f - (float)emask[b * LE + e]) * NEGV;
        mx = fmaxf(mx, v[j]);
    }
    __shared__ float sm[256];
    sm[t] = mx;
    __syncthreads();
    for (int s = 128; s > 0; s >>= 1) {
        if (t < s) sm[t] = fmaxf(sm[t], sm[t + s]);
        __syncthreads();
    }
    mx = sm[0];
    __syncthreads();

    float sum = 0.0f;
#pragma unroll
    for (int j = 0; j < 4; j++) {
        v[j] = expf(v[j] - mx);
        sum += v[j];
    }
    sm[t] = sum;
    __syncthreads();
    for (int s = 128; s > 0; s >>= 1) {
        if (t < s) sm[t] += sm[t + s];
        __syncthreads();
    }
    float inv = 1.0f / sm[0];
#pragma unroll
    for (int j = 0; j < 4; j++) row[t + j * 256] = v[j] * inv;
}

// ---------------- final head (unchanged) ----------------
__global__ void head_kernel(const float* __restrict__ r1, const float* __restrict__ r2,
                            const float* __restrict__ Wm, const float* __restrict__ bm,
                            const float* __restrict__ Wo, const float* __restrict__ bo,
                            float* __restrict__ out)
{
    const int b = blockIdx.x;
    const int t = threadIdx.x;
    __shared__ float mv[4 * DD];
    __shared__ float outacc[3];
    if (t < DD) {
        float a = r1[(size_t)b * DD + t];
        float c = r2[(size_t)b * DD + t];
        mv[t] = a;
        mv[DD + t] = c;
        mv[2 * DD + t] = a * c;
        mv[3 * DD + t] = a - c;
    }
    if (t < 3) outacc[t] = 0.0f;
    __syncthreads();

    float acc = bm[t];
#pragma unroll 8
    for (int k = 0; k < 4 * DD; k++) acc = fmaf(mv[k], Wm[(size_t)k * MM + t], acc);
    float h = fmaxf(acc, 0.0f);

#pragma unroll
    for (int i = 0; i < 3; i++) atomicAdd(&outacc[i], h * Wo[(size_t)t * 3 + i]);
    __syncthreads();
    if (t < 3) out[(size_t)b * 3 + t] = outacc[t] + bo[t];
}

// ---------------- launch ----------------
extern "C" void kernel_launch(void* const* d_in, const int* in_sizes, int n_in,
                              void* d_out, int out_size)
{
    const float* criteria = (const float*)d_in[0];
    const float* ehr      = (const float*)d_in[1];
    const int*   cmask    = (const int*)d_in[2];
    const int*   emask    = (const int*)d_in[3];
    const float* Wa       = (const float*)d_in[4];
    const float* ba       = (const float*)d_in[5];
    const float* Wr       = (const float*)d_in[6];
    const float* br       = (const float*)d_in[7];
    const float* Wm       = (const float*)d_in[8];
    const float* bm       = (const float*)d_in[9];
    const float* Wo       = (const float*)d_in[10];
    const float* bo       = (const float*)d_in[11];
    float* out = (float*)d_out;

    float* base;
    cudaGetSymbolAddress((void**)&base, g_scratch);
    float* p_c     = base + OFF_C;
    float* p_e     = base + OFF_E;
    float* p_align = base + OFF_ALIGN;
    float* p_beta  = base + OFF_E;     // alias: e dead after align GEMM
    float* p_attc  = base + OFF_C;     // alias: c dead after align GEMM
    float* p_atte  = base + OFF_ATTE;
    float* p_r1    = base + OFF_R1;
    float* p_r2    = base + OFF_R2;

    // 1) c = relu(criteria @ Wa + ba)  (flat over B*LC rows)
    mm_nn<<<dim3(DD / BN, (BB * LC) / BM, 1), 256>>>(
        criteria, Wa, ba, p_c, DD, DD, 0, 0, 0, 1);
    // 2) e = relu(ehr @ Wa + ba)
    mm_nn<<<dim3(DD / BN, (BB * LE) / BM, 1), 256>>>(
        ehr, Wa, ba, p_e, DD, DD, 0, 0, 0, 1);
    // 3) align = c @ e^T  (batched NT)
    mm_nt<<<dim3(LE / BN, LC / BM, BB), 256>>>(
        p_c, p_e, p_align, LE, DD,
        (size_t)LC * DD, (size_t)LE * DD, (size_t)LC * LE);
    // 4) beta (softmax over Lc, masked by criteria_mask) -> aliases e
    beta_kernel<<<dim3(LE / 32, BB), dim3(32, 8)>>>(p_align, p_beta, cmask);
    // 5) alpha in-place (softmax over Le, masked by ehr_mask)
    alpha_kernel<<<dim3(LC, BB), 256>>>(p_align, emask);
    // 6) att_c = alpha @ ehr   (batched NN, K=LE) -> aliases c
    mm_nn<<<dim3(DD / BN, LC / BM, BB), 256>>>(
        p_align, ehr, nullptr, p_attc, DD, LE,
        (size_t)LC * LE, (size_t)LE * DD, (size_t)LC * DD, 0);
    // 7) att_e = beta^T @ criteria  (batched TN, K=LC, lda=LE)
    mm_tn<<<dim3(DD / BN, LE / BM, BB), 256>>>(
        p_beta, criteria, p_atte, DD, LC, LE,
        (size_t)LC * LE, (size_t)LC * DD, (size_t)LE * DD);
    // 8) r1, r2 (fused concat GEMM + relu + row-sum)
    cudaMemsetAsync(p_r1, 0, (size_t)2 * BB * DD * sizeof(float));
    mm_concat_relu_rowsum<<<dim3(DD / BN, LC / BM, BB), 256>>>(
        p_attc, criteria, Wr, br, p_r1, LC);
    mm_concat_relu_rowsum<<<dim3(DD / BN, LE / BM, BB), 256>>>(
        p_atte, ehr, Wr, br, p_r2, LE);
    // 9) head
    head_kernel<<<BB, MM>>>(p_r1, p_r2, Wm, bm, Wo, bo, out);
}

// round 5
// speedup vs baseline: 3.4934x; 1.8906x over previous
#include <cuda_runtime.h>
#include <cuda_bf16.h>
#include <math.h>
#include <stdint.h>

// Problem constants
#define BB 128
#define LC 256
#define LE 1024
#define DD 256
#define MM 512
#define NEGV (-1e9f)

// GEMM tile config: BM=BN=128, BK=16, 256 threads, 8 warps @ 64x32
#define BM 128
#define BN 128
#define BK 16
#define PA 132
#define PB 132

// ---------------- scratch (single device global; aliased regions) ----------------
#define OFF_C     ((size_t)0)
#define OFF_E     ((size_t)BB * LC * DD)
#define OFF_ALIGN (OFF_E + (size_t)BB * LE * DD)
#define OFF_ATTE  (OFF_ALIGN + (size_t)BB * LC * LE)
#define OFF_R1    (OFF_ATTE + (size_t)BB * LE * DD)
#define OFF_R2    (OFF_R1 + (size_t)BB * DD)
#define SCRATCH_FLOATS (OFF_R2 + (size_t)BB * DD)

__device__ float g_scratch[SCRATCH_FLOATS];   // ~416 MB total

// ---------------- tf32 helpers ----------------
// Round-to-nearest tf32 conversion (unbiased; truncation was 20x worse).
__device__ __forceinline__ uint32_t f2tf32(float x) {
    uint32_t r;
    asm("cvt.rna.tf32.f32 %0, %1;" : "=r"(r) : "f"(x));
    return r;
}

__device__ __forceinline__ void mma_tf32(float* c, const uint32_t* a, const uint32_t* b) {
    asm volatile(
        "mma.sync.aligned.m16n8k8.row.col.f32.tf32.tf32.f32 "
        "{%0,%1,%2,%3}, {%4,%5,%6,%7}, {%8,%9}, {%0,%1,%2,%3};"
        : "+f"(c[0]), "+f"(c[1]), "+f"(c[2]), "+f"(c[3])
        : "r"(a[0]), "r"(a[1]), "r"(a[2]), "r"(a[3]), "r"(b[0]), "r"(b[1]));
}

// Warp tile 64x32: wm=(wid&1)*64, wn=(wid>>1)*32. acc[4][4][4].
__device__ __forceinline__ void mma_compute(
    const uint32_t (*As)[PA], const uint32_t (*Bs)[PB],
    int lane, int wm, int wn, float acc[4][4][4])
{
    const int c4 = lane & 3;
    const int g8 = lane >> 2;
#pragma unroll
    for (int ks = 0; ks < BK; ks += 8) {
        uint32_t af[4][4];
#pragma unroll
        for (int mi = 0; mi < 4; mi++) {
            int mrow = wm + mi * 16 + g8;
            af[mi][0] = As[ks + c4][mrow];
            af[mi][1] = As[ks + c4][mrow + 8];
            af[mi][2] = As[ks + c4 + 4][mrow];
            af[mi][3] = As[ks + c4 + 4][mrow + 8];
        }
        uint32_t bf[4][2];
#pragma unroll
        for (int ni = 0; ni < 4; ni++) {
            int ncol = wn + ni * 8 + g8;
            bf[ni][0] = Bs[ks + c4][ncol];
            bf[ni][1] = Bs[ks + c4 + 4][ncol];
        }
#pragma unroll
        for (int mi = 0; mi < 4; mi++)
#pragma unroll
            for (int ni = 0; ni < 4; ni++)
                mma_tf32(acc[mi][ni], af[mi], bf[ni]);
    }
}

__device__ __forceinline__ uint4 f4tf32(float4 v) {
    return make_uint4(f2tf32(v.x), f2tf32(v.y), f2tf32(v.z), f2tf32(v.w));
}

// ---------------- GEMM kernels ----------------

// C = [relu](A @ B + bias). A (M,K) rm, B (K,N) rm. Batched by strides.
__global__ __launch_bounds__(256) void mm_nn(
    const float* __restrict__ A, const float* __restrict__ B,
    const float* __restrict__ bias, float* __restrict__ C,
    int N, int K, size_t sA, size_t sB, size_t sC, int doRelu)
{
    __shared__ uint32_t As[BK][PA];
    __shared__ uint32_t Bs[BK][PB];
    const int tid = threadIdx.x;
    const int lane = tid & 31, wid = tid >> 5;
    const int wm = (wid & 1) * 64, wn = (wid >> 1) * 32;
    const int m0 = blockIdx.y * BM, n0 = blockIdx.x * BN;
    A += (size_t)blockIdx.z * sA;
    B += (size_t)blockIdx.z * sB;
    C += (size_t)blockIdx.z * sC;

    const int aM = tid >> 2, aK4 = (tid & 3) * 4;     // A: transpose path
    const int bN4 = (tid & 31) * 4, bK = tid >> 5;    // B: direct path

    float4 ra[2], rb[2];
    ra[0] = *(const float4*)&A[(size_t)(m0 + aM) * K + aK4];
    ra[1] = *(const float4*)&A[(size_t)(m0 + aM + 64) * K + aK4];
    rb[0] = *(const float4*)&B[(size_t)bK * N + n0 + bN4];
    rb[1] = *(const float4*)&B[(size_t)(bK + 8) * N + n0 + bN4];

    float acc[4][4][4] = {};
    const int nIters = K / BK;
    for (int it = 0; it < nIters; it++) {
#pragma unroll
        for (int i = 0; i < 2; i++) {
            int m = aM + i * 64;
            As[aK4 + 0][m] = f2tf32(ra[i].x);
            As[aK4 + 1][m] = f2tf32(ra[i].y);
            As[aK4 + 2][m] = f2tf32(ra[i].z);
            As[aK4 + 3][m] = f2tf32(ra[i].w);
            *(uint4*)&Bs[bK + i * 8][bN4] = f4tf32(rb[i]);
        }
        __syncthreads();
        if (it + 1 < nIters) {
            int k0 = (it + 1) * BK;
            ra[0] = *(const float4*)&A[(size_t)(m0 + aM) * K + k0 + aK4];
            ra[1] = *(const float4*)&A[(size_t)(m0 + aM + 64) * K + k0 + aK4];
            rb[0] = *(const float4*)&B[(size_t)(k0 + bK) * N + n0 + bN4];
            rb[1] = *(const float4*)&B[(size_t)(k0 + bK + 8) * N + n0 + bN4];
        }
        mma_compute(As, Bs, lane, wm, wn, acc);
        __syncthreads();
    }
    const int c4 = lane & 3, g8 = lane >> 2;
#pragma unroll
    for (int mi = 0; mi < 4; mi++)
#pragma unroll
        for (int ni = 0; ni < 4; ni++) {
            int row = m0 + wm + mi * 16 + g8;
            int col = n0 + wn + ni * 8 + 2 * c4;
            float v0 = acc[mi][ni][0], v1 = acc[mi][ni][1];
            float v2 = acc[mi][ni][2], v3 = acc[mi][ni][3];
            if (bias) { float b0 = bias[col], b1 = bias[col + 1]; v0 += b0; v1 += b1; v2 += b0; v3 += b1; }
            if (doRelu) {
                v0 = fmaxf(v0, 0.f); v1 = fmaxf(v1, 0.f);
                v2 = fmaxf(v2, 0.f); v3 = fmaxf(v3, 0.f);
            }
            *(float2*)&C[(size_t)row * N + col] = make_float2(v0, v1);
            *(float2*)&C[(size_t)(row + 8) * N + col] = make_float2(v2, v3);
        }
}

// C = A @ B^T. A (M,K) rm, B (N,K) rm. Batched.
__global__ __launch_bounds__(256) void mm_nt(
    const float* __restrict__ A, const float* __restrict__ B, float* __restrict__ C,
    int N, int K, size_t sA, size_t sB, size_t sC)
{
    __shared__ uint32_t As[BK][PA];
    __shared__ uint32_t Bs[BK][PB];
    const int tid = threadIdx.x;
    const int lane = tid & 31, wid = tid >> 5;
    const int wm = (wid & 1) * 64, wn = (wid >> 1) * 32;
    const int m0 = blockIdx.y * BM, n0 = blockIdx.x * BN;
    A += (size_t)blockIdx.z * sA;
    B += (size_t)blockIdx.z * sB;
    C += (size_t)blockIdx.z * sC;

    const int aM = tid >> 2, aK4 = (tid & 3) * 4;   // transpose path (both A and B)

    float4 ra[2], rb[2];
    ra[0] = *(const float4*)&A[(size_t)(m0 + aM) * K + aK4];
    ra[1] = *(const float4*)&A[(size_t)(m0 + aM + 64) * K + aK4];
    rb[0] = *(const float4*)&B[(size_t)(n0 + aM) * K + aK4];
    rb[1] = *(const float4*)&B[(size_t)(n0 + aM + 64) * K + aK4];

    float acc[4][4][4] = {};
    const int nIters = K / BK;
    for (int it = 0; it < nIters; it++) {
#pragma unroll
        for (int i = 0; i < 2; i++) {
            int m = aM + i * 64;
            As[aK4 + 0][m] = f2tf32(ra[i].x);
            As[aK4 + 1][m] = f2tf32(ra[i].y);
            As[aK4 + 2][m] = f2tf32(ra[i].z);
            As[aK4 + 3][m] = f2tf32(ra[i].w);
            Bs[aK4 + 0][m] = f2tf32(rb[i].x);
            Bs[aK4 + 1][m] = f2tf32(rb[i].y);
            Bs[aK4 + 2][m] = f2tf32(rb[i].z);
            Bs[aK4 + 3][m] = f2tf32(rb[i].w);
        }
        __syncthreads();
        if (it + 1 < nIters) {
            int k0 = (it + 1) * BK;
            ra[0] = *(const float4*)&A[(size_t)(m0 + aM) * K + k0 + aK4];
            ra[1] = *(const float4*)&A[(size_t)(m0 + aM + 64) * K + k0 + aK4];
            rb[0] = *(const float4*)&B[(size_t)(n0 + aM) * K + k0 + aK4];
            rb[1] = *(const float4*)&B[(size_t)(n0 + aM + 64) * K + k0 + aK4];
        }
        mma_compute(As, Bs, lane, wm, wn, acc);
        __syncthreads();
    }
    const int c4 = lane & 3, g8 = lane >> 2;
#pragma unroll
    for (int mi = 0; mi < 4; mi++)
#pragma unroll
        for (int ni = 0; ni < 4; ni++) {
            int row = m0 + wm + mi * 16 + g8;
            int col = n0 + wn + ni * 8 + 2 * c4;
            *(float2*)&C[(size_t)row * N + col] = make_float2(acc[mi][ni][0], acc[mi][ni][1]);
            *(float2*)&C[(size_t)(row + 8) * N + col] = make_float2(acc[mi][ni][2], acc[mi][ni][3]);
        }
}

// C = A^T @ B. A stored (K, lda) rm, B (K,N) rm. Batched.
__global__ __launch_bounds__(256) void mm_tn(
    const float* __restrict__ A, const float* __restrict__ B, float* __restrict__ C,
    int N, int K, int lda, size_t sA, size_t sB, size_t sC)
{
    __shared__ uint32_t As[BK][PA];
    __shared__ uint32_t Bs[BK][PB];
    const int tid = threadIdx.x;
    const int lane = tid & 31, wid = tid >> 5;
    const int wm = (wid & 1) * 64, wn = (wid >> 1) * 32;
    const int m0 = blockIdx.y * BM, n0 = blockIdx.x * BN;
    A += (size_t)blockIdx.z * sA;
    B += (size_t)blockIdx.z * sB;
    C += (size_t)blockIdx.z * sC;

    const int xM4 = (tid & 31) * 4, xK = tid >> 5;  // direct path (both A and B)

    float4 ra[2], rb[2];
    ra[0] = *(const float4*)&A[(size_t)xK * lda + m0 + xM4];
    ra[1] = *(const float4*)&A[(size_t)(xK + 8) * lda + m0 + xM4];
    rb[0] = *(const float4*)&B[(size_t)xK * N + n0 + xM4];
    rb[1] = *(const float4*)&B[(size_t)(xK + 8) * N + n0 + xM4];

    float acc[4][4][4] = {};
    const int nIters = K / BK;
    for (int it = 0; it < nIters; it++) {
#pragma unroll
        for (int i = 0; i < 2; i++) {
            *(uint4*)&As[xK + i * 8][xM4] = f4tf32(ra[i]);
            *(uint4*)&Bs[xK + i * 8][xM4] = f4tf32(rb[i]);
        }
        __syncthreads();
        if (it + 1 < nIters) {
            int k0 = (it + 1) * BK;
            ra[0] = *(const float4*)&A[(size_t)(k0 + xK) * lda + m0 + xM4];
            ra[1] = *(const float4*)&A[(size_t)(k0 + xK + 8) * lda + m0 + xM4];
            rb[0] = *(const float4*)&B[(size_t)(k0 + xK) * N + n0 + xM4];
            rb[1] = *(const float4*)&B[(size_t)(k0 + xK + 8) * N + n0 + xM4];
        }
        mma_compute(As, Bs, lane, wm, wn, acc);
        __syncthreads();
    }
    const int c4 = lane & 3, g8 = lane >> 2;
#pragma unroll
    for (int mi = 0; mi < 4; mi++)
#pragma unroll
        for (int ni = 0; ni < 4; ni++) {
            int row = m0 + wm + mi * 16 + g8;
            int col = n0 + wn + ni * 8 + 2 * c4;
            *(float2*)&C[(size_t)row * N + col] = make_float2(acc[mi][ni][0], acc[mi][ni][1]);
            *(float2*)&C[(size_t)(row + 8) * N + col] = make_float2(acc[mi][ni][2], acc[mi][ni][3]);
        }
}

// r[b,n] += sum_m relu( [X1|X2][m,:] @ Wr + br )[n]   (K = 2D = 512, N = D = 256)
__global__ __launch_bounds__(256) void mm_concat_relu_rowsum(
    const float* __restrict__ X1, const float* __restrict__ X2,
    const float* __restrict__ Wr, const float* __restrict__ br,
    float* __restrict__ r, int L)
{
    __shared__ uint32_t As[BK][PA];
    __shared__ uint32_t Bs[BK][PB];
    __shared__ float colsum[BN];
    const int tid = threadIdx.x;
    const int lane = tid & 31, wid = tid >> 5;
    const int wm = (wid & 1) * 64, wn = (wid >> 1) * 32;
    const int b = blockIdx.z;
    const int m0 = blockIdx.y * BM, n0 = blockIdx.x * BN;
    const float* A1 = X1 + (size_t)b * L * DD;
    const float* A2 = X2 + (size_t)b * L * DD;

    if (tid < BN) colsum[tid] = 0.0f;

    const int aM = tid >> 2, aK4 = (tid & 3) * 4;
    const int bN4 = (tid & 31) * 4, bK = tid >> 5;

    float4 ra[2], rb[2];
    ra[0] = *(const float4*)&A1[(size_t)(m0 + aM) * DD + aK4];
    ra[1] = *(const float4*)&A1[(size_t)(m0 + aM + 64) * DD + aK4];
    rb[0] = *(const float4*)&Wr[(size_t)bK * DD + n0 + bN4];
    rb[1] = *(const float4*)&Wr[(size_t)(bK + 8) * DD + n0 + bN4];

    float acc[4][4][4] = {};
    const int nIters = (2 * DD) / BK;
    for (int it = 0; it < nIters; it++) {
#pragma unroll
        for (int i = 0; i < 2; i++) {
            int m = aM + i * 64;
            As[aK4 + 0][m] = f2tf32(ra[i].x);
            As[aK4 + 1][m] = f2tf32(ra[i].y);
            As[aK4 + 2][m] = f2tf32(ra[i].z);
            As[aK4 + 3][m] = f2tf32(ra[i].w);
            *(uint4*)&Bs[bK + i * 8][bN4] = f4tf32(rb[i]);
        }
        __syncthreads();
        if (it + 1 < nIters) {
            int k0 = (it + 1) * BK;
            const float* Asrc = (k0 < DD) ? A1 : A2;
            int kk = (k0 < DD) ? k0 : k0 - DD;
            ra[0] = *(const float4*)&Asrc[(size_t)(m0 + aM) * DD + kk + aK4];
            ra[1] = *(const float4*)&Asrc[(size_t)(m0 + aM + 64) * DD + kk + aK4];
            rb[0] = *(const float4*)&Wr[(size_t)(k0 + bK) * DD + n0 + bN4];
            rb[1] = *(const float4*)&Wr[(size_t)(k0 + bK + 8) * DD + n0 + bN4];
        }
        mma_compute(As, Bs, lane, wm, wn, acc);
        __syncthreads();
    }
    // epilogue: relu(acc + bias), column sums
    const int c4 = lane & 3;
#pragma unroll
    for (int ni = 0; ni < 4; ni++) {
        int col = wn + ni * 8 + 2 * c4;
        float b0 = br[n0 + col], b1 = br[n0 + col + 1];
        float s0 = 0.f, s1 = 0.f;
#pragma unroll
        for (int mi = 0; mi < 4; mi++) {
            s0 += fmaxf(acc[mi][ni][0] + b0, 0.f) + fmaxf(acc[mi][ni][2] + b0, 0.f);
            s1 += fmaxf(acc[mi][ni][1] + b1, 0.f) + fmaxf(acc[mi][ni][3] + b1, 0.f);
        }
        atomicAdd(&colsum[col], s0);
        atomicAdd(&colsum[col + 1], s1);
    }
    __syncthreads();
    if (tid < BN) atomicAdd(&r[(size_t)b * DD + n0 + tid], colsum[tid]);
}

// ---------------- softmax kernels ----------------

__global__ void beta_kernel(const float* __restrict__ align_, float* __restrict__ beta,
                            const int* __restrict__ cmask)
{
    const int b = blockIdx.y;
    const int e = blockIdx.x * 32 + threadIdx.x;
    const int tx = threadIdx.x, ty = threadIdx.y;
    const float* base = align_ + (size_t)b * LC * LE + e;
    float* outb = beta + (size_t)b * LC * LE + e;

    float vals[LC / 8];
    float mx = -INFINITY;
#pragma unroll
    for (int i = 0; i < LC / 8; i++) {
        int l = ty + i * 8;
        float v = base[(size_t)l * LE] + (1.0f - (float)cmask[b * LC + l]) * NEGV;
        vals[i] = v;
        mx = fmaxf(mx, v);
    }
    __shared__ float red[8][32];
    red[ty][tx] = mx;
    __syncthreads();
    if (ty == 0) {
        float m2 = red[0][tx];
#pragma unroll
        for (int i = 1; i < 8; i++) m2 = fmaxf(m2, red[i][tx]);
        red[0][tx] = m2;
    }
    __syncthreads();
    mx = red[0][tx];
    __syncthreads();

    float s = 0.0f;
#pragma unroll
    for (int i = 0; i < LC / 8; i++) {
        vals[i] = expf(vals[i] - mx);
        s += vals[i];
    }
    red[ty][tx] = s;
    __syncthreads();
    if (ty == 0) {
        float s2 = 0.0f;
#pragma unroll
        for (int i = 0; i < 8; i++) s2 += red[i][tx];
        red[0][tx] = s2;
    }
    __syncthreads();
    float inv = 1.0f / red[0][tx];
#pragma unroll
    for (int i = 0; i < LC / 8; i++) {
        int l = ty + i * 8;
        outb[(size_t)l * LE] = vals[i] * inv;
    }
}

__global__ void alpha_kernel(float* __restrict__ align_, const int* __restrict__ emask)
{
    const int b = blockIdx.y;
    const int l = blockIdx.x;
    const int t = threadIdx.x;
    float* row = align_ + ((size_t)b * LC + l) * LE;

    float v[4];
    float mx = -INFINITY;
#pragma unroll
    for (int j = 0; j < 4; j++) {
        int e = t + j * 256;
        v[j] = row[e] + (1.0f - (float)emask[b * LE + e]) * NEGV;
        mx = fmaxf(mx, v[j]);
    }
    __shared__ float sm[256];
    sm[t] = mx;
    __syncthreads();
    for (int s = 128; s > 0; s >>= 1) {
        if (t < s) sm[t] = fmaxf(sm[t], sm[t + s]);
        __syncthreads();
    }
    mx = sm[0];
    __syncthreads();

    float sum = 0.0f;
#pragma unroll
    for (int j = 0; j < 4; j++) {
        v[j] = expf(v[j] - mx);
        sum += v[j];
    }
    sm[t] = sum;
    __syncthreads();
    for (int s = 128; s > 0; s >>= 1) {
        if (t < s) sm[t] += sm[t + s];
        __syncthreads();
    }
    float inv = 1.0f / sm[0];
#pragma unroll
    for (int j = 0; j < 4; j++) row[t + j * 256] = v[j] * inv;
}

// ---------------- final head ----------------
__global__ void head_kernel(const float* __restrict__ r1, const float* __restrict__ r2,
                            const float* __restrict__ Wm, const float* __restrict__ bm,
                            const float* __restrict__ Wo, const float* __restrict__ bo,
                            float* __restrict__ out)
{
    const int b = blockIdx.x;
    const int t = threadIdx.x;
    __shared__ float mv[4 * DD];
    __shared__ float outacc[3];
    if (t < DD) {
        float a = r1[(size_t)b * DD + t];
        float c = r2[(size_t)b * DD + t];
        mv[t] = a;
        mv[DD + t] = c;
        mv[2 * DD + t] = a * c;
        mv[3 * DD + t] = a - c;
    }
    if (t < 3) outacc[t] = 0.0f;
    __syncthreads();

    float acc = bm[t];
#pragma unroll 8
    for (int k = 0; k < 4 * DD; k++) acc = fmaf(mv[k], Wm[(size_t)k * MM + t], acc);
    float h = fmaxf(acc, 0.0f);

#pragma unroll
    for (int i = 0; i < 3; i++) atomicAdd(&outacc[i], h * Wo[(size_t)t * 3 + i]);
    __syncthreads();
    if (t < 3) out[(size_t)b * 3 + t] = outacc[t] + bo[t];
}

// ---------------- launch ----------------
extern "C" void kernel_launch(void* const* d_in, const int* in_sizes, int n_in,
                              void* d_out, int out_size)
{
    const float* criteria = (const float*)d_in[0];
    const float* ehr      = (const float*)d_in[1];
    const int*   cmask    = (const int*)d_in[2];
    const int*   emask    = (const int*)d_in[3];
    const float* Wa       = (const float*)d_in[4];
    const float* ba       = (const float*)d_in[5];
    const float* Wr       = (const float*)d_in[6];
    const float* br       = (const float*)d_in[7];
    const float* Wm       = (const float*)d_in[8];
    const float* bm       = (const float*)d_in[9];
    const float* Wo       = (const float*)d_in[10];
    const float* bo       = (const float*)d_in[11];
    float* out = (float*)d_out;

    float* base;
    cudaGetSymbolAddress((void**)&base, g_scratch);
    float* p_c     = base + OFF_C;
    float* p_e     = base + OFF_E;
    float* p_align = base + OFF_ALIGN;
    float* p_beta  = base + OFF_E;     // alias: e dead after align GEMM
    float* p_attc  = base + OFF_C;     // alias: c dead after align GEMM
    float* p_atte  = base + OFF_ATTE;
    float* p_r1    = base + OFF_R1;
    float* p_r2    = base + OFF_R2;

    // 1) c = relu(criteria @ Wa + ba)  (flat over B*LC rows)
    mm_nn<<<dim3(DD / BN, (BB * LC) / BM, 1), 256>>>(
        criteria, Wa, ba, p_c, DD, DD, 0, 0, 0, 1);
    // 2) e = relu(ehr @ Wa + ba)
    mm_nn<<<dim3(DD / BN, (BB * LE) / BM, 1), 256>>>(
        ehr, Wa, ba, p_e, DD, DD, 0, 0, 0, 1);
    // 3) align = c @ e^T  (batched NT)
    mm_nt<<<dim3(LE / BN, LC / BM, BB), 256>>>(
        p_c, p_e, p_align, LE, DD,
        (size_t)LC * DD, (size_t)LE * DD, (size_t)LC * LE);
    // 4) beta (softmax over Lc, masked by criteria_mask) -> aliases e
    beta_kernel<<<dim3(LE / 32, BB), dim3(32, 8)>>>(p_align, p_beta, cmask);
    // 5) alpha in-place (softmax over Le, masked by ehr_mask)
    alpha_kernel<<<dim3(LC, BB), 256>>>(p_align, emask);
    // 6) att_c = alpha @ ehr   (batched NN, K=LE) -> aliases c
    mm_nn<<<dim3(DD / BN, LC / BM, BB), 256>>>(
        p_align, ehr, nullptr, p_attc, DD, LE,
        (size_t)LC * LE, (size_t)LE * DD, (size_t)LC * DD, 0);
    // 7) att_e = beta^T @ criteria  (batched TN, K=LC, lda=LE)
    mm_tn<<<dim3(DD / BN, LE / BM, BB), 256>>>(
        p_beta, criteria, p_atte, DD, LC, LE,
        (size_t)LC * LE, (size_t)LC * DD, (size_t)LE * DD);
    // 8) r1, r2 (fused concat GEMM + relu + row-sum)
    cudaMemsetAsync(p_r1, 0, (size_t)2 * BB * DD * sizeof(float));
    mm_concat_relu_rowsum<<<dim3(DD / BN, LC / BM, BB), 256>>>(
        p_attc, criteria, Wr, br, p_r1, LC);
    mm_concat_relu_rowsum<<<dim3(DD / BN, LE / BM, BB), 256>>>(
        p_atte, ehr, Wr, br, p_r2, LE);
    // 9) head
    head_kernel<<<BB, MM>>>(p_r1, p_r2, Wm, bm, Wo, bo, out);
}

// round 6
// speedup vs baseline: 4.9786x; 1.4252x over previous
#include <cuda_runtime.h>
#include <cuda_bf16.h>
#include <math.h>
#include <stdint.h>

// Problem constants
#define BB 128
#define LC 256
#define LE 1024
#define DD 256
#define MM 512
#define NEGV (-1e9f)

// GEMM tile config: BM=BN=128, BKE=32 elements (16 bf16x2 words), 256 thr, 8 warps @ 64x32
#define BM 128
#define BN 128
#define BKE 32
#define PA 132
#define PB 132

// ---------------- scratch (single device global; aliased regions) ----------------
#define OFF_C     ((size_t)0)
#define OFF_E     ((size_t)BB * LC * DD)
#define OFF_ALIGN (OFF_E + (size_t)BB * LE * DD)
#define OFF_ATTE  (OFF_ALIGN + (size_t)BB * LC * LE)
#define OFF_R1    (OFF_ATTE + (size_t)BB * LE * DD)
#define OFF_R2    (OFF_R1 + (size_t)BB * DD)
#define SCRATCH_FLOATS (OFF_R2 + (size_t)BB * DD)

__device__ float g_scratch[SCRATCH_FLOATS];   // ~416 MB total

// ---------------- bf16 helpers ----------------
// Pack two consecutive-k floats into one bf16x2 word (round-to-nearest, unbiased).
__device__ __forceinline__ uint32_t pk(float lo, float hi) {
    __nv_bfloat162 h = __floats2bfloat162_rn(lo, hi);
    return *reinterpret_cast<uint32_t*>(&h);
}
// Pairwise pack: word j = (a.j, b.j) — a is k-row, b is k+1-row.
__device__ __forceinline__ uint4 pk4(float4 a, float4 b) {
    return make_uint4(pk(a.x, b.x), pk(a.y, b.y), pk(a.z, b.z), pk(a.w, b.w));
}

__device__ __forceinline__ void mma_bf16(float* c, const uint32_t* a, const uint32_t* b) {
    asm volatile(
        "mma.sync.aligned.m16n8k16.row.col.f32.bf16.bf16.f32 "
        "{%0,%1,%2,%3}, {%4,%5,%6,%7}, {%8,%9}, {%0,%1,%2,%3};"
        : "+f"(c[0]), "+f"(c[1]), "+f"(c[2]), "+f"(c[3])
        : "r"(a[0]), "r"(a[1]), "r"(a[2]), "r"(a[3]), "r"(b[0]), "r"(b[1]));
}

// Warp tile 64x32: wm=(wid&1)*64, wn=(wid>>1)*32. acc[4][4][4].
// As/Bs words: [w][m], word w covers k = 2w, 2w+1. 16 words = 32 k elements.
__device__ __forceinline__ void mma_compute(
    const uint32_t (*As)[PA], const uint32_t (*Bs)[PB],
    int lane, int wm, int wn, float acc[4][4][4])
{
    const int c4 = lane & 3;
    const int g8 = lane >> 2;
#pragma unroll
    for (int ks = 0; ks < 16; ks += 8) {    // two k16 steps (word units)
        uint32_t af[4][4];
#pragma unroll
        for (int mi = 0; mi < 4; mi++) {
            int mrow = wm + mi * 16 + g8;
            af[mi][0] = As[ks + c4][mrow];
            af[mi][1] = As[ks + c4][mrow + 8];
            af[mi][2] = As[ks + c4 + 4][mrow];
            af[mi][3] = As[ks + c4 + 4][mrow + 8];
        }
        uint32_t bf[4][2];
#pragma unroll
        for (int ni = 0; ni < 4; ni++) {
            int ncol = wn + ni * 8 + g8;
            bf[ni][0] = Bs[ks + c4][ncol];
            bf[ni][1] = Bs[ks + c4 + 4][ncol];
        }
#pragma unroll
        for (int mi = 0; mi < 4; mi++)
#pragma unroll
            for (int ni = 0; ni < 4; ni++)
                mma_bf16(acc[mi][ni], af[mi], bf[ni]);
    }
}

// ---------------- GEMM kernels ----------------

// C = [relu](A @ B + bias). A (M,K) rm, B (K,N) rm. Batched by strides.
__global__ __launch_bounds__(256) void mm_nn(
    const float* __restrict__ A, const float* __restrict__ B,
    const float* __restrict__ bias, float* __restrict__ C,
    int N, int K, size_t sA, size_t sB, size_t sC, int doRelu)
{
    __shared__ uint32_t As[16][PA];
    __shared__ uint32_t Bs[16][PB];
    const int tid = threadIdx.x;
    const int lane = tid & 31, wid = tid >> 5;
    const int wm = (wid & 1) * 64, wn = (wid >> 1) * 32;
    const int m0 = blockIdx.y * BM, n0 = blockIdx.x * BN;
    A += (size_t)blockIdx.z * sA;
    B += (size_t)blockIdx.z * sB;
    C += (size_t)blockIdx.z * sC;

    const int aM = tid >> 2, aK = (tid & 3) * 8, aW = (tid & 3) * 4;  // A transpose path
    const int bN4 = (tid & 31) * 4, bP = tid >> 5;                    // B pair-row path

    float4 ra[4], rb[4];
    ra[0] = *(const float4*)&A[(size_t)(m0 + aM) * K + aK];
    ra[1] = *(const float4*)&A[(size_t)(m0 + aM) * K + aK + 4];
    ra[2] = *(const float4*)&A[(size_t)(m0 + aM + 64) * K + aK];
    ra[3] = *(const float4*)&A[(size_t)(m0 + aM + 64) * K + aK + 4];
    rb[0] = *(const float4*)&B[(size_t)(2 * bP) * N + n0 + bN4];
    rb[1] = *(const float4*)&B[(size_t)(2 * bP + 1) * N + n0 + bN4];
    rb[2] = *(const float4*)&B[(size_t)(2 * bP + 16) * N + n0 + bN4];
    rb[3] = *(const float4*)&B[(size_t)(2 * bP + 17) * N + n0 + bN4];

    float acc[4][4][4] = {};
    const int nIters = K / BKE;
    for (int it = 0; it < nIters; it++) {
        As[aW + 0][aM] = pk(ra[0].x, ra[0].y);
        As[aW + 1][aM] = pk(ra[0].z, ra[0].w);
        As[aW + 2][aM] = pk(ra[1].x, ra[1].y);
        As[aW + 3][aM] = pk(ra[1].z, ra[1].w);
        As[aW + 0][aM + 64] = pk(ra[2].x, ra[2].y);
        As[aW + 1][aM + 64] = pk(ra[2].z, ra[2].w);
        As[aW + 2][aM + 64] = pk(ra[3].x, ra[3].y);
        As[aW + 3][aM + 64] = pk(ra[3].z, ra[3].w);
        *(uint4*)&Bs[bP][bN4] = pk4(rb[0], rb[1]);
        *(uint4*)&Bs[bP + 8][bN4] = pk4(rb[2], rb[3]);
        __syncthreads();
        if (it + 1 < nIters) {
            int k0 = (it + 1) * BKE;
            ra[0] = *(const float4*)&A[(size_t)(m0 + aM) * K + k0 + aK];
            ra[1] = *(const float4*)&A[(size_t)(m0 + aM) * K + k0 + aK + 4];
            ra[2] = *(const float4*)&A[(size_t)(m0 + aM + 64) * K + k0 + aK];
            ra[3] = *(const float4*)&A[(size_t)(m0 + aM + 64) * K + k0 + aK + 4];
            rb[0] = *(const float4*)&B[(size_t)(k0 + 2 * bP) * N + n0 + bN4];
            rb[1] = *(const float4*)&B[(size_t)(k0 + 2 * bP + 1) * N + n0 + bN4];
            rb[2] = *(const float4*)&B[(size_t)(k0 + 2 * bP + 16) * N + n0 + bN4];
            rb[3] = *(const float4*)&B[(size_t)(k0 + 2 * bP + 17) * N + n0 + bN4];
        }
        mma_compute(As, Bs, lane, wm, wn, acc);
        __syncthreads();
    }
    const int c4 = lane & 3, g8 = lane >> 2;
#pragma unroll
    for (int mi = 0; mi < 4; mi++)
#pragma unroll
        for (int ni = 0; ni < 4; ni++) {
            int row = m0 + wm + mi * 16 + g8;
            int col = n0 + wn + ni * 8 + 2 * c4;
            float v0 = acc[mi][ni][0], v1 = acc[mi][ni][1];
            float v2 = acc[mi][ni][2], v3 = acc[mi][ni][3];
            if (bias) { float b0 = bias[col], b1 = bias[col + 1]; v0 += b0; v1 += b1; v2 += b0; v3 += b1; }
            if (doRelu) {
                v0 = fmaxf(v0, 0.f); v1 = fmaxf(v1, 0.f);
                v2 = fmaxf(v2, 0.f); v3 = fmaxf(v3, 0.f);
            }
            *(float2*)&C[(size_t)row * N + col] = make_float2(v0, v1);
            *(float2*)&C[(size_t)(row + 8) * N + col] = make_float2(v2, v3);
        }
}

// C = A @ B^T. A (M,K) rm, B (N,K) rm. Batched.
__global__ __launch_bounds__(256) void mm_nt(
    const float* __restrict__ A, const float* __restrict__ B, float* __restrict__ C,
    int N, int K, size_t sA, size_t sB, size_t sC)
{
    __shared__ uint32_t As[16][PA];
    __shared__ uint32_t Bs[16][PB];
    const int tid = threadIdx.x;
    const int lane = tid & 31, wid = tid >> 5;
    const int wm = (wid & 1) * 64, wn = (wid >> 1) * 32;
    const int m0 = blockIdx.y * BM, n0 = blockIdx.x * BN;
    A += (size_t)blockIdx.z * sA;
    B += (size_t)blockIdx.z * sB;
    C += (size_t)blockIdx.z * sC;

    const int aM = tid >> 2, aK = (tid & 3) * 8, aW = (tid & 3) * 4;  // transpose both

    float4 ra[4], rb[4];
    ra[0] = *(const float4*)&A[(size_t)(m0 + aM) * K + aK];
    ra[1] = *(const float4*)&A[(size_t)(m0 + aM) * K + aK + 4];
    ra[2] = *(const float4*)&A[(size_t)(m0 + aM + 64) * K + aK];
    ra[3] = *(const float4*)&A[(size_t)(m0 + aM + 64) * K + aK + 4];
    rb[0] = *(const float4*)&B[(size_t)(n0 + aM) * K + aK];
    rb[1] = *(const float4*)&B[(size_t)(n0 + aM) * K + aK + 4];
    rb[2] = *(const float4*)&B[(size_t)(n0 + aM + 64) * K + aK];
    rb[3] = *(const float4*)&B[(size_t)(n0 + aM + 64) * K + aK + 4];

    float acc[4][4][4] = {};
    const int nIters = K / BKE;
    for (int it = 0; it < nIters; it++) {
        As[aW + 0][aM] = pk(ra[0].x, ra[0].y);
        As[aW + 1][aM] = pk(ra[0].z, ra[0].w);
        As[aW + 2][aM] = pk(ra[1].x, ra[1].y);
        As[aW + 3][aM] = pk(ra[1].z, ra[1].w);
        As[aW + 0][aM + 64] = pk(ra[2].x, ra[2].y);
        As[aW + 1][aM + 64] = pk(ra[2].z, ra[2].w);
        As[aW + 2][aM + 64] = pk(ra[3].x, ra[3].y);
        As[aW + 3][aM + 64] = pk(ra[3].z, ra[3].w);
        Bs[aW + 0][aM] = pk(rb[0].x, rb[0].y);
        Bs[aW + 1][aM] = pk(rb[0].z, rb[0].w);
        Bs[aW + 2][aM] = pk(rb[1].x, rb[1].y);
        Bs[aW + 3][aM] = pk(rb[1].z, rb[1].w);
        Bs[aW + 0][aM + 64] = pk(rb[2].x, rb[2].y);
        Bs[aW + 1][aM + 64] = pk(rb[2].z, rb[2].w);
        Bs[aW + 2][aM + 64] = pk(rb[3].x, rb[3].y);
        Bs[aW + 3][aM + 64] = pk(rb[3].z, rb[3].w);
        __syncthreads();
        if (it + 1 < nIters) {
            int k0 = (it + 1) * BKE;
            ra[0] = *(const float4*)&A[(size_t)(m0 + aM) * K + k0 + aK];
            ra[1] = *(const float4*)&A[(size_t)(m0 + aM) * K + k0 + aK + 4];
            ra[2] = *(const float4*)&A[(size_t)(m0 + aM + 64) * K + k0 + aK];
            ra[3] = *(const float4*)&A[(size_t)(m0 + aM + 64) * K + k0 + aK + 4];
            rb[0] = *(const float4*)&B[(size_t)(n0 + aM) * K + k0 + aK];
            rb[1] = *(const float4*)&B[(size_t)(n0 + aM) * K + k0 + aK + 4];
            rb[2] = *(const float4*)&B[(size_t)(n0 + aM + 64) * K + k0 + aK];
            rb[3] = *(const float4*)&B[(size_t)(n0 + aM + 64) * K + k0 + aK + 4];
        }
        mma_compute(As, Bs, lane, wm, wn, acc);
        __syncthreads();
    }
    const int c4 = lane & 3, g8 = lane >> 2;
#pragma unroll
    for (int mi = 0; mi < 4; mi++)
#pragma unroll
        for (int ni = 0; ni < 4; ni++) {
            int row = m0 + wm + mi * 16 + g8;
            int col = n0 + wn + ni * 8 + 2 * c4;
            *(float2*)&C[(size_t)row * N + col] = make_float2(acc[mi][ni][0], acc[mi][ni][1]);
            *(float2*)&C[(size_t)(row + 8) * N + col] = make_float2(acc[mi][ni][2], acc[mi][ni][3]);
        }
}

// C = A^T @ B. A stored (K, lda) rm, B (K,N) rm. Batched.
__global__ __launch_bounds__(256) void mm_tn(
    const float* __restrict__ A, const float* __restrict__ B, float* __restrict__ C,
    int N, int K, int lda, size_t sA, size_t sB, size_t sC)
{
    __shared__ uint32_t As[16][PA];
    __shared__ uint32_t Bs[16][PB];
    const int tid = threadIdx.x;
    const int lane = tid & 31, wid = tid >> 5;
    const int wm = (wid & 1) * 64, wn = (wid >> 1) * 32;
    const int m0 = blockIdx.y * BM, n0 = blockIdx.x * BN;
    A += (size_t)blockIdx.z * sA;
    B += (size_t)blockIdx.z * sB;
    C += (size_t)blockIdx.z * sC;

    const int xM4 = (tid & 31) * 4, xP = tid >> 5;  // pair-row path both

    float4 ra[4], rb[4];
    ra[0] = *(const float4*)&A[(size_t)(2 * xP) * lda + m0 + xM4];
    ra[1] = *(const float4*)&A[(size_t)(2 * xP + 1) * lda + m0 + xM4];
    ra[2] = *(const float4*)&A[(size_t)(2 * xP + 16) * lda + m0 + xM4];
    ra[3] = *(const float4*)&A[(size_t)(2 * xP + 17) * lda + m0 + xM4];
    rb[0] = *(const float4*)&B[(size_t)(2 * xP) * N + n0 + xM4];
    rb[1] = *(const float4*)&B[(size_t)(2 * xP + 1) * N + n0 + xM4];
    rb[2] = *(const float4*)&B[(size_t)(2 * xP + 16) * N + n0 + xM4];
    rb[3] = *(const float4*)&B[(size_t)(2 * xP + 17) * N + n0 + xM4];

    float acc[4][4][4] = {};
    const int nIters = K / BKE;
    for (int it = 0; it < nIters; it++) {
        *(uint4*)&As[xP][xM4] = pk4(ra[0], ra[1]);
        *(uint4*)&As[xP + 8][xM4] = pk4(ra[2], ra[3]);
        *(uint4*)&Bs[xP][xM4] = pk4(rb[0], rb[1]);
        *(uint4*)&Bs[xP + 8][xM4] = pk4(rb[2], rb[3]);
        __syncthreads();
        if (it + 1 < nIters) {
            int k0 = (it + 1) * BKE;
            ra[0] = *(const float4*)&A[(size_t)(k0 + 2 * xP) * lda + m0 + xM4];
            ra[1] = *(const float4*)&A[(size_t)(k0 + 2 * xP + 1) * lda + m0 + xM4];
            ra[2] = *(const float4*)&A[(size_t)(k0 + 2 * xP + 16) * lda + m0 + xM4];
            ra[3] = *(const float4*)&A[(size_t)(k0 + 2 * xP + 17) * lda + m0 + xM4];
            rb[0] = *(const float4*)&B[(size_t)(k0 + 2 * xP) * N + n0 + xM4];
            rb[1] = *(const float4*)&B[(size_t)(k0 + 2 * xP + 1) * N + n0 + xM4];
            rb[2] = *(const float4*)&B[(size_t)(k0 + 2 * xP + 16) * N + n0 + xM4];
            rb[3] = *(const float4*)&B[(size_t)(k0 + 2 * xP + 17) * N + n0 + xM4];
        }
        mma_compute(As, Bs, lane, wm, wn, acc);
        __syncthreads();
    }
    const int c4 = lane & 3, g8 = lane >> 2;
#pragma unroll
    for (int mi = 0; mi < 4; mi++)
#pragma unroll
        for (int ni = 0; ni < 4; ni++) {
            int row = m0 + wm + mi * 16 + g8;
            int col = n0 + wn + ni * 8 + 2 * c4;
            *(float2*)&C[(size_t)row * N + col] = make_float2(acc[mi][ni][0], acc[mi][ni][1]);
            *(float2*)&C[(size_t)(row + 8) * N + col] = make_float2(acc[mi][ni][2], acc[mi][ni][3]);
        }
}

// r[b,n] += sum_m relu( [X1|X2][m,:] @ Wr + br )[n]   (K = 2D = 512, N = D = 256)
__global__ __launch_bounds__(256) void mm_concat_relu_rowsum(
    const float* __restrict__ X1, const float* __restrict__ X2,
    const float* __restrict__ Wr, const float* __restrict__ br,
    float* __restrict__ r, int L)
{
    __shared__ uint32_t As[16][PA];
    __shared__ uint32_t Bs[16][PB];
    __shared__ float colsum[BN];
    const int tid = threadIdx.x;
    const int lane = tid & 31, wid = tid >> 5;
    const int wm = (wid & 1) * 64, wn = (wid >> 1) * 32;
    const int b = blockIdx.z;
    const int m0 = blockIdx.y * BM, n0 = blockIdx.x * BN;
    const float* A1 = X1 + (size_t)b * L * DD;
    const float* A2 = X2 + (size_t)b * L * DD;

    if (tid < BN) colsum[tid] = 0.0f;

    const int aM = tid >> 2, aK = (tid & 3) * 8, aW = (tid & 3) * 4;
    const int bN4 = (tid & 31) * 4, bP = tid >> 5;

    float4 ra[4], rb[4];
    ra[0] = *(const float4*)&A1[(size_t)(m0 + aM) * DD + aK];
    ra[1] = *(const float4*)&A1[(size_t)(m0 + aM) * DD + aK + 4];
    ra[2] = *(const float4*)&A1[(size_t)(m0 + aM + 64) * DD + aK];
    ra[3] = *(const float4*)&A1[(size_t)(m0 + aM + 64) * DD + aK + 4];
    rb[0] = *(const float4*)&Wr[(size_t)(2 * bP) * DD + n0 + bN4];
    rb[1] = *(const float4*)&Wr[(size_t)(2 * bP + 1) * DD + n0 + bN4];
    rb[2] = *(const float4*)&Wr[(size_t)(2 * bP + 16) * DD + n0 + bN4];
    rb[3] = *(const float4*)&Wr[(size_t)(2 * bP + 17) * DD + n0 + bN4];

    float acc[4][4][4] = {};
    const int nIters = (2 * DD) / BKE;   // 16
    for (int it = 0; it < nIters; it++) {
        As[aW + 0][aM] = pk(ra[0].x, ra[0].y);
        As[aW + 1][aM] = pk(ra[0].z, ra[0].w);
        As[aW + 2][aM] = pk(ra[1].x, ra[1].y);
        As[aW + 3][aM] = pk(ra[1].z, ra[1].w);
        As[aW + 0][aM + 64] = pk(ra[2].x, ra[2].y);
        As[aW + 1][aM + 64] = pk(ra[2].z, ra[2].w);
        As[aW + 2][aM + 64] = pk(ra[3].x, ra[3].y);
        As[aW + 3][aM + 64] = pk(ra[3].z, ra[3].w);
        *(uint4*)&Bs[bP][bN4] = pk4(rb[0], rb[1]);
        *(uint4*)&Bs[bP + 8][bN4] = pk4(rb[2], rb[3]);
        __syncthreads();
        if (it + 1 < nIters) {
            int k0 = (it + 1) * BKE;
            const float* Asrc = (k0 < DD) ? A1 : A2;
            int kk = (k0 < DD) ? k0 : k0 - DD;
            ra[0] = *(const float4*)&Asrc[(size_t)(m0 + aM) * DD + kk + aK];
            ra[1] = *(const float4*)&Asrc[(size_t)(m0 + aM) * DD + kk + aK + 4];
            ra[2] = *(const float4*)&Asrc[(size_t)(m0 + aM + 64) * DD + kk + aK];
            ra[3] = *(const float4*)&Asrc[(size_t)(m0 + aM + 64) * DD + kk + aK + 4];
            rb[0] = *(const float4*)&Wr[(size_t)(k0 + 2 * bP) * DD + n0 + bN4];
            rb[1] = *(const float4*)&Wr[(size_t)(k0 + 2 * bP + 1) * DD + n0 + bN4];
            rb[2] = *(const float4*)&Wr[(size_t)(k0 + 2 * bP + 16) * DD + n0 + bN4];
            rb[3] = *(const float4*)&Wr[(size_t)(k0 + 2 * bP + 17) * DD + n0 + bN4];
        }
        mma_compute(As, Bs, lane, wm, wn, acc);
        __syncthreads();
    }
    // epilogue: relu(acc + bias), column sums
    const int c4 = lane & 3;
#pragma unroll
    for (int ni = 0; ni < 4; ni++) {
        int col = wn + ni * 8 + 2 * c4;
        float b0 = br[n0 + col], b1 = br[n0 + col + 1];
        float s0 = 0.f, s1 = 0.f;
#pragma unroll
        for (int mi = 0; mi < 4; mi++) {
            s0 += fmaxf(acc[mi][ni][0] + b0, 0.f) + fmaxf(acc[mi][ni][2] + b0, 0.f);
            s1 += fmaxf(acc[mi][ni][1] + b1, 0.f) + fmaxf(acc[mi][ni][3] + b1, 0.f);
        }
        atomicAdd(&colsum[col], s0);
        atomicAdd(&colsum[col + 1], s1);
    }
    __syncthreads();
    if (tid < BN) atomicAdd(&r[(size_t)b * DD + n0 + tid], colsum[tid]);
}

// ---------------- softmax kernels ----------------

__global__ void beta_kernel(const float* __restrict__ align_, float* __restrict__ beta,
                            const int* __restrict__ cmask)
{
    const int b = blockIdx.y;
    const int e = blockIdx.x * 32 + threadIdx.x;
    const int tx = threadIdx.x, ty = threadIdx.y;
    const float* base = align_ + (size_t)b * LC * LE + e;
    float* outb = beta + (size_t)b * LC * LE + e;

    float vals[LC / 8];
    float mx = -INFINITY;
#pragma unroll
    for (int i = 0; i < LC / 8; i++) {
        int l = ty + i * 8;
        float v = base[(size_t)l * LE] + (1.0f - (float)cmask[b * LC + l]) * NEGV;
        vals[i] = v;
        mx = fmaxf(mx, v);
    }
    __shared__ float red[8][32];
    red[ty][tx] = mx;
    __syncthreads();
    if (ty == 0) {
        float m2 = red[0][tx];
#pragma unroll
        for (int i = 1; i < 8; i++) m2 = fmaxf(m2, red[i][tx]);
        red[0][tx] = m2;
    }
    __syncthreads();
    mx = red[0][tx];
    __syncthreads();

    float s = 0.0f;
#pragma unroll
    for (int i = 0; i < LC / 8; i++) {
        vals[i] = expf(vals[i] - mx);
        s += vals[i];
    }
    red[ty][tx] = s;
    __syncthreads();
    if (ty == 0) {
        float s2 = 0.0f;
#pragma unroll
        for (int i = 0; i < 8; i++) s2 += red[i][tx];
        red[0][tx] = s2;
    }
    __syncthreads();
    float inv = 1.0f / red[0][tx];
#pragma unroll
    for (int i = 0; i < LC / 8; i++) {
        int l = ty + i * 8;
        outb[(size_t)l * LE] = vals[i] * inv;
    }
}

__global__ void alpha_kernel(float* __restrict__ align_, const int* __restrict__ emask)
{
    const int b = blockIdx.y;
    const int l = blockIdx.x;
    const int t = threadIdx.x;
    float* row = align_ + ((size_t)b * LC + l) * LE;

    float v[4];
    float mx = -INFINITY;
#pragma unroll
    for (int j = 0; j < 4; j++) {
        int e = t + j * 256;
        v[j] = row[e] + (1.0f - (float)emask[b * LE + e]) * NEGV;
        mx = fmaxf(mx, v[j]);
    }
    __shared__ float sm[256];
    sm[t] = mx;
    __syncthreads();
    for (int s = 128; s > 0; s >>= 1) {
        if (t < s) sm[t] = fmaxf(sm[t], sm[t + s]);
        __syncthreads();
    }
    mx = sm[0];
    __syncthreads();

    float sum = 0.0f;
#pragma unroll
    for (int j = 0; j < 4; j++) {
        v[j] = expf(v[j] - mx);
        sum += v[j];
    }
    sm[t] = sum;
    __syncthreads();
    for (int s = 128; s > 0; s >>= 1) {
        if (t < s) sm[t] += sm[t + s];
        __syncthreads();
    }
    float inv = 1.0f / sm[0];
#pragma unroll
    for (int j = 0; j < 4; j++) row[t + j * 256] = v[j] * inv;
}

// ---------------- final head ----------------
__global__ void head_kernel(const float* __restrict__ r1, const float* __restrict__ r2,
                            const float* __restrict__ Wm, const float* __restrict__ bm,
                            const float* __restrict__ Wo, const float* __restrict__ bo,
                            float* __restrict__ out)
{
    const int b = blockIdx.x;
    const int t = threadIdx.x;
    __shared__ float mv[4 * DD];
    __shared__ float outacc[3];
    if (t < DD) {
        float a = r1[(size_t)b * DD + t];
        float c = r2[(size_t)b * DD + t];
        mv[t] = a;
        mv[DD + t] = c;
        mv[2 * DD + t] = a * c;
        mv[3 * DD + t] = a - c;
    }
    if (t < 3) outacc[t] = 0.0f;
    __syncthreads();

    float acc = bm[t];
#pragma unroll 8
    for (int k = 0; k < 4 * DD; k++) acc = fmaf(mv[k], Wm[(size_t)k * MM + t], acc);
    float h = fmaxf(acc, 0.0f);

#pragma unroll
    for (int i = 0; i < 3; i++) atomicAdd(&outacc[i], h * Wo[(size_t)t * 3 + i]);
    __syncthreads();
    if (t < 3) out[(size_t)b * 3 + t] = outacc[t] + bo[t];
}

// ---------------- launch ----------------
extern "C" void kernel_launch(void* const* d_in, const int* in_sizes, int n_in,
                              void* d_out, int out_size)
{
    const float* criteria = (const float*)d_in[0];
    const float* ehr      = (const float*)d_in[1];
    const int*   cmask    = (const int*)d_in[2];
    const int*   emask    = (const int*)d_in[3];
    const float* Wa       = (const float*)d_in[4];
    const float* ba       = (const float*)d_in[5];
    const float* Wr       = (const float*)d_in[6];
    const float* br       = (const float*)d_in[7];
    const float* Wm       = (const float*)d_in[8];
    const float* bm       = (const float*)d_in[9];
    const float* Wo       = (const float*)d_in[10];
    const float* bo       = (const float*)d_in[11];
    float* out = (float*)d_out;

    float* base;
    cudaGetSymbolAddress((void**)&base, g_scratch);
    float* p_c     = base + OFF_C;
    float* p_e     = base + OFF_E;
    float* p_align = base + OFF_ALIGN;
    float* p_beta  = base + OFF_E;     // alias: e dead after align GEMM
    float* p_attc  = base + OFF_C;     // alias: c dead after align GEMM
    float* p_atte  = base + OFF_ATTE;
    float* p_r1    = base + OFF_R1;
    float* p_r2    = base + OFF_R2;

    // 1) c = relu(criteria @ Wa + ba)  (flat over B*LC rows)
    mm_nn<<<dim3(DD / BN, (BB * LC) / BM, 1), 256>>>(
        criteria, Wa, ba, p_c, DD, DD, 0, 0, 0, 1);
    // 2) e = relu(ehr @ Wa + ba)
    mm_nn<<<dim3(DD / BN, (BB * LE) / BM, 1), 256>>>(
        ehr, Wa, ba, p_e, DD, DD, 0, 0, 0, 1);
    // 3) align = c @ e^T  (batched NT)
    mm_nt<<<dim3(LE / BN, LC / BM, BB), 256>>>(
        p_c, p_e, p_align, LE, DD,
        (size_t)LC * DD, (size_t)LE * DD, (size_t)LC * LE);
    // 4) beta (softmax over Lc, masked by criteria_mask) -> aliases e
    beta_kernel<<<dim3(LE / 32, BB), dim3(32, 8)>>>(p_align, p_beta, cmask);
    // 5) alpha in-place (softmax over Le, masked by ehr_mask)
    alpha_kernel<<<dim3(LC, BB), 256>>>(p_align, emask);
    // 6) att_c = alpha @ ehr   (batched NN, K=LE) -> aliases c
    mm_nn<<<dim3(DD / BN, LC / BM, BB), 256>>>(
        p_align, ehr, nullptr, p_attc, DD, LE,
        (size_t)LC * LE, (size_t)LE * DD, (size_t)LC * DD, 0);
    // 7) att_e = beta^T @ criteria  (batched TN, K=LC, lda=LE)
    mm_tn<<<dim3(DD / BN, LE / BM, BB), 256>>>(
        p_beta, criteria, p_atte, DD, LC, LE,
        (size_t)LC * LE, (size_t)LC * DD, (size_t)LE * DD);
    // 8) r1, r2 (fused concat GEMM + relu + row-sum)
    cudaMemsetAsync(p_r1, 0, (size_t)2 * BB * DD * sizeof(float));
    mm_concat_relu_rowsum<<<dim3(DD / BN, LC / BM, BB), 256>>>(
        p_attc, criteria, Wr, br, p_r1, LC);
    mm_concat_relu_rowsum<<<dim3(DD / BN, LE / BM, BB), 256>>>(
        p_atte, ehr, Wr, br, p_r2, LE);
    // 9) head
    head_kernel<<<BB, MM>>>(p_r1, p_r2, Wm, bm, Wo, bo, out);
}

// round 7
// speedup vs baseline: 5.2126x; 1.0470x over previous
#include <cuda_runtime.h>
#include <cuda_bf16.h>
#include <math.h>
#include <stdint.h>

// Problem constants
#define BB 128
#define LC 256
#define LE 1024
#define DD 256
#define MM 512
#define NEGV (-1e9f)

// GEMM tile config: BM=BN=128, BKE=32 elements (16 bf16x2 words), 256 thr, 8 warps @ 64x32
#define BM 128
#define BN 128
#define BKE 32
#define PA 132
#define PB 132

// ---------------- scratch (single device global; aliased regions; float units) ----------
#define HCLD ((size_t)BB * LC * DD / 2)   // bf16 (B,LC,D) buffer in float units
#define HLED ((size_t)BB * LE * DD / 2)   // bf16 (B,LE,D)
#define HLCE ((size_t)BB * LC * LE / 2)   // bf16 (B,LC,LE)
#define OFF_CB    ((size_t)0)                         // c bf16 -> later attc
#define OFF_EB    (OFF_CB + HCLD)                     // e bf16 -> later beta
#define OFF_ALIGN (OFF_EB + HLED)                     // align fp32
#define OFF_ALPHA (OFF_ALIGN + (size_t)BB * LC * LE)  // alpha bf16
#define OFF_ATTE  (OFF_ALPHA + HLCE)                  // atte bf16
#define OFF_R1    (OFF_ATTE + HLED)
#define OFF_R2    (OFF_R1 + (size_t)BB * DD)
#define SCRATCH_FLOATS (OFF_R2 + (size_t)BB * DD)

__device__ float g_scratch[SCRATCH_FLOATS];   // ~355 MB

// ---------------- helpers ----------------
__device__ __forceinline__ uint32_t pk(float lo, float hi) {
    __nv_bfloat162 h = __floats2bfloat162_rn(lo, hi);
    return *reinterpret_cast<uint32_t*>(&h);
}
__device__ __forceinline__ uint4 pk4(float4 a, float4 b) {
    return make_uint4(pk(a.x, b.x), pk(a.y, b.y), pk(a.z, b.z), pk(a.w, b.w));
}
__device__ __forceinline__ uint32_t prmt(uint32_t a, uint32_t b, uint32_t c) {
    uint32_t d;
    asm("prmt.b32 %0, %1, %2, %3;" : "=r"(d) : "r"(a), "r"(b), "r"(c));
    return d;
}

__device__ __forceinline__ void mma_bf16(float* c, const uint32_t* a, const uint32_t* b) {
    asm volatile(
        "mma.sync.aligned.m16n8k16.row.col.f32.bf16.bf16.f32 "
        "{%0,%1,%2,%3}, {%4,%5,%6,%7}, {%8,%9}, {%0,%1,%2,%3};"
        : "+f"(c[0]), "+f"(c[1]), "+f"(c[2]), "+f"(c[3])
        : "r"(a[0]), "r"(a[1]), "r"(a[2]), "r"(a[3]), "r"(b[0]), "r"(b[1]));
}

// Warp tile 64x32: wm=(wid&1)*64, wn=(wid>>1)*32. acc[4][4][4].
__device__ __forceinline__ void mma_compute(
    const uint32_t (*As)[PA], const uint32_t (*Bs)[PB],
    int lane, int wm, int wn, float acc[4][4][4])
{
    const int c4 = lane & 3;
    const int g8 = lane >> 2;
#pragma unroll
    for (int ks = 0; ks < 16; ks += 8) {
        uint32_t af[4][4];
#pragma unroll
        for (int mi = 0; mi < 4; mi++) {
            int mrow = wm + mi * 16 + g8;
            af[mi][0] = As[ks + c4][mrow];
            af[mi][1] = As[ks + c4][mrow + 8];
            af[mi][2] = As[ks + c4 + 4][mrow];
            af[mi][3] = As[ks + c4 + 4][mrow + 8];
        }
        uint32_t bf[4][2];
#pragma unroll
        for (int ni = 0; ni < 4; ni++) {
            int ncol = wn + ni * 8 + g8;
            bf[ni][0] = Bs[ks + c4][ncol];
            bf[ni][1] = Bs[ks + c4 + 4][ncol];
        }
#pragma unroll
        for (int mi = 0; mi < 4; mi++)
#pragma unroll
            for (int ni = 0; ni < 4; ni++)
                mma_bf16(acc[mi][ni], af[mi], bf[ni]);
    }
}

// ---------------- GEMM kernels ----------------

// Steps 1,2: C_bf16 = relu(A_f32 @ B_f32 + bias). A (M,K) rm, B (K,N) rm.
__global__ __launch_bounds__(256) void mm_proj(
    const float* __restrict__ A, const float* __restrict__ B,
    const float* __restrict__ bias, __nv_bfloat16* __restrict__ C, int N, int K)
{
    __shared__ uint32_t As[16][PA];
    __shared__ uint32_t Bs[16][PB];
    const int tid = threadIdx.x;
    const int lane = tid & 31, wid = tid >> 5;
    const int wm = (wid & 1) * 64, wn = (wid >> 1) * 32;
    const int m0 = blockIdx.y * BM, n0 = blockIdx.x * BN;

    const int aM = tid >> 2, aK = (tid & 3) * 8, aW = (tid & 3) * 4;
    const int bN4 = (tid & 31) * 4, bP = tid >> 5;

    float4 ra[4], rb[4];
    ra[0] = *(const float4*)&A[(size_t)(m0 + aM) * K + aK];
    ra[1] = *(const float4*)&A[(size_t)(m0 + aM) * K + aK + 4];
    ra[2] = *(const float4*)&A[(size_t)(m0 + aM + 64) * K + aK];
    ra[3] = *(const float4*)&A[(size_t)(m0 + aM + 64) * K + aK + 4];
    rb[0] = *(const float4*)&B[(size_t)(2 * bP) * N + n0 + bN4];
    rb[1] = *(const float4*)&B[(size_t)(2 * bP + 1) * N + n0 + bN4];
    rb[2] = *(const float4*)&B[(size_t)(2 * bP + 16) * N + n0 + bN4];
    rb[3] = *(const float4*)&B[(size_t)(2 * bP + 17) * N + n0 + bN4];

    float acc[4][4][4] = {};
    const int nIters = K / BKE;
    for (int it = 0; it < nIters; it++) {
        As[aW + 0][aM] = pk(ra[0].x, ra[0].y);
        As[aW + 1][aM] = pk(ra[0].z, ra[0].w);
        As[aW + 2][aM] = pk(ra[1].x, ra[1].y);
        As[aW + 3][aM] = pk(ra[1].z, ra[1].w);
        As[aW + 0][aM + 64] = pk(ra[2].x, ra[2].y);
        As[aW + 1][aM + 64] = pk(ra[2].z, ra[2].w);
        As[aW + 2][aM + 64] = pk(ra[3].x, ra[3].y);
        As[aW + 3][aM + 64] = pk(ra[3].z, ra[3].w);
        *(uint4*)&Bs[bP][bN4] = pk4(rb[0], rb[1]);
        *(uint4*)&Bs[bP + 8][bN4] = pk4(rb[2], rb[3]);
        __syncthreads();
        if (it + 1 < nIters) {
            int k0 = (it + 1) * BKE;
            ra[0] = *(const float4*)&A[(size_t)(m0 + aM) * K + k0 + aK];
            ra[1] = *(const float4*)&A[(size_t)(m0 + aM) * K + k0 + aK + 4];
            ra[2] = *(const float4*)&A[(size_t)(m0 + aM + 64) * K + k0 + aK];
            ra[3] = *(const float4*)&A[(size_t)(m0 + aM + 64) * K + k0 + aK + 4];
            rb[0] = *(const float4*)&B[(size_t)(k0 + 2 * bP) * N + n0 + bN4];
            rb[1] = *(const float4*)&B[(size_t)(k0 + 2 * bP + 1) * N + n0 + bN4];
            rb[2] = *(const float4*)&B[(size_t)(k0 + 2 * bP + 16) * N + n0 + bN4];
            rb[3] = *(const float4*)&B[(size_t)(k0 + 2 * bP + 17) * N + n0 + bN4];
        }
        mma_compute(As, Bs, lane, wm, wn, acc);
        __syncthreads();
    }
    const int c4 = lane & 3, g8 = lane >> 2;
#pragma unroll
    for (int mi = 0; mi < 4; mi++)
#pragma unroll
        for (int ni = 0; ni < 4; ni++) {
            int row = m0 + wm + mi * 16 + g8;
            int col = n0 + wn + ni * 8 + 2 * c4;
            float b0 = bias[col], b1 = bias[col + 1];
            float v0 = fmaxf(acc[mi][ni][0] + b0, 0.f);
            float v1 = fmaxf(acc[mi][ni][1] + b1, 0.f);
            float v2 = fmaxf(acc[mi][ni][2] + b0, 0.f);
            float v3 = fmaxf(acc[mi][ni][3] + b1, 0.f);
            *(uint32_t*)&C[(size_t)row * N + col] = pk(v0, v1);
            *(uint32_t*)&C[(size_t)(row + 8) * N + col] = pk(v2, v3);
        }
}

// Step 3: align_f32 = c_bf16 @ e_bf16^T. A (M,K) rm bf16, B (N,K) rm bf16. Batched.
__global__ __launch_bounds__(256) void mm_align(
    const __nv_bfloat16* __restrict__ A, const __nv_bfloat16* __restrict__ Bm,
    float* __restrict__ C, int N, int K, size_t sA, size_t sB, size_t sC)
{
    __shared__ uint32_t As[16][PA];
    __shared__ uint32_t Bs[16][PB];
    const int tid = threadIdx.x;
    const int lane = tid & 31, wid = tid >> 5;
    const int wm = (wid & 1) * 64, wn = (wid >> 1) * 32;
    const int m0 = blockIdx.y * BM, n0 = blockIdx.x * BN;
    A += (size_t)blockIdx.z * sA;
    Bm += (size_t)blockIdx.z * sB;
    C += (size_t)blockIdx.z * sC;

    const int aM = tid >> 2, aK = (tid & 3) * 8, aW = (tid & 3) * 4;

    uint4 qa[2], qb[2];
    qa[0] = *(const uint4*)(A + (size_t)(m0 + aM) * K + aK);
    qa[1] = *(const uint4*)(A + (size_t)(m0 + aM + 64) * K + aK);
    qb[0] = *(const uint4*)(Bm + (size_t)(n0 + aM) * K + aK);
    qb[1] = *(const uint4*)(Bm + (size_t)(n0 + aM + 64) * K + aK);

    float acc[4][4][4] = {};
    const int nIters = K / BKE;
    for (int it = 0; it < nIters; it++) {
        As[aW + 0][aM] = qa[0].x; As[aW + 1][aM] = qa[0].y;
        As[aW + 2][aM] = qa[0].z; As[aW + 3][aM] = qa[0].w;
        As[aW + 0][aM + 64] = qa[1].x; As[aW + 1][aM + 64] = qa[1].y;
        As[aW + 2][aM + 64] = qa[1].z; As[aW + 3][aM + 64] = qa[1].w;
        Bs[aW + 0][aM] = qb[0].x; Bs[aW + 1][aM] = qb[0].y;
        Bs[aW + 2][aM] = qb[0].z; Bs[aW + 3][aM] = qb[0].w;
        Bs[aW + 0][aM + 64] = qb[1].x; Bs[aW + 1][aM + 64] = qb[1].y;
        Bs[aW + 2][aM + 64] = qb[1].z; Bs[aW + 3][aM + 64] = qb[1].w;
        __syncthreads();
        if (it + 1 < nIters) {
            int k0 = (it + 1) * BKE;
            qa[0] = *(const uint4*)(A + (size_t)(m0 + aM) * K + k0 + aK);
            qa[1] = *(const uint4*)(A + (size_t)(m0 + aM + 64) * K + k0 + aK);
            qb[0] = *(const uint4*)(Bm + (size_t)(n0 + aM) * K + k0 + aK);
            qb[1] = *(const uint4*)(Bm + (size_t)(n0 + aM + 64) * K + k0 + aK);
        }
        mma_compute(As, Bs, lane, wm, wn, acc);
        __syncthreads();
    }
    const int c4 = lane & 3, g8 = lane >> 2;
#pragma unroll
    for (int mi = 0; mi < 4; mi++)
#pragma unroll
        for (int ni = 0; ni < 4; ni++) {
            int row = m0 + wm + mi * 16 + g8;
            int col = n0 + wn + ni * 8 + 2 * c4;
            *(float2*)&C[(size_t)row * N + col] = make_float2(acc[mi][ni][0], acc[mi][ni][1]);
            *(float2*)&C[(size_t)(row + 8) * N + col] = make_float2(acc[mi][ni][2], acc[mi][ni][3]);
        }
}

// Step 6: attc_bf16 = alpha_bf16 @ ehr_f32. A (M,K) rm bf16, B (K,N) rm f32. Batched.
__global__ __launch_bounds__(256) void mm_attc(
    const __nv_bfloat16* __restrict__ A, const float* __restrict__ B,
    __nv_bfloat16* __restrict__ C, int N, int K, size_t sA, size_t sB, size_t sC)
{
    __shared__ uint32_t As[16][PA];
    __shared__ uint32_t Bs[16][PB];
    const int tid = threadIdx.x;
    const int lane = tid & 31, wid = tid >> 5;
    const int wm = (wid & 1) * 64, wn = (wid >> 1) * 32;
    const int m0 = blockIdx.y * BM, n0 = blockIdx.x * BN;
    A += (size_t)blockIdx.z * sA;
    B += (size_t)blockIdx.z * sB;
    C += (size_t)blockIdx.z * sC;

    const int aM = tid >> 2, aK = (tid & 3) * 8, aW = (tid & 3) * 4;
    const int bN4 = (tid & 31) * 4, bP = tid >> 5;

    uint4 qa[2];
    float4 rb[4];
    qa[0] = *(const uint4*)(A + (size_t)(m0 + aM) * K + aK);
    qa[1] = *(const uint4*)(A + (size_t)(m0 + aM + 64) * K + aK);
    rb[0] = *(const float4*)&B[(size_t)(2 * bP) * N + n0 + bN4];
    rb[1] = *(const float4*)&B[(size_t)(2 * bP + 1) * N + n0 + bN4];
    rb[2] = *(const float4*)&B[(size_t)(2 * bP + 16) * N + n0 + bN4];
    rb[3] = *(const float4*)&B[(size_t)(2 * bP + 17) * N + n0 + bN4];

    float acc[4][4][4] = {};
    const int nIters = K / BKE;
    for (int it = 0; it < nIters; it++) {
        As[aW + 0][aM] = qa[0].x; As[aW + 1][aM] = qa[0].y;
        As[aW + 2][aM] = qa[0].z; As[aW + 3][aM] = qa[0].w;
        As[aW + 0][aM + 64] = qa[1].x; As[aW + 1][aM + 64] = qa[1].y;
        As[aW + 2][aM + 64] = qa[1].z; As[aW + 3][aM + 64] = qa[1].w;
        *(uint4*)&Bs[bP][bN4] = pk4(rb[0], rb[1]);
        *(uint4*)&Bs[bP + 8][bN4] = pk4(rb[2], rb[3]);
        __syncthreads();
        if (it + 1 < nIters) {
            int k0 = (it + 1) * BKE;
            qa[0] = *(const uint4*)(A + (size_t)(m0 + aM) * K + k0 + aK);
            qa[1] = *(const uint4*)(A + (size_t)(m0 + aM + 64) * K + k0 + aK);
            rb[0] = *(const float4*)&B[(size_t)(k0 + 2 * bP) * N + n0 + bN4];
            rb[1] = *(const float4*)&B[(size_t)(k0 + 2 * bP + 1) * N + n0 + bN4];
            rb[2] = *(const float4*)&B[(size_t)(k0 + 2 * bP + 16) * N + n0 + bN4];
            rb[3] = *(const float4*)&B[(size_t)(k0 + 2 * bP + 17) * N + n0 + bN4];
        }
        mma_compute(As, Bs, lane, wm, wn, acc);
        __syncthreads();
    }
    const int c4 = lane & 3, g8 = lane >> 2;
#pragma unroll
    for (int mi = 0; mi < 4; mi++)
#pragma unroll
        for (int ni = 0; ni < 4; ni++) {
            int row = m0 + wm + mi * 16 + g8;
            int col = n0 + wn + ni * 8 + 2 * c4;
            *(uint32_t*)&C[(size_t)row * N + col] = pk(acc[mi][ni][0], acc[mi][ni][1]);
            *(uint32_t*)&C[(size_t)(row + 8) * N + col] = pk(acc[mi][ni][2], acc[mi][ni][3]);
        }
}

// Step 7: atte_bf16 = beta_bf16^T @ criteria_f32. A stored (K, lda) rm bf16, B (K,N) rm f32.
__global__ __launch_bounds__(256) void mm_atte(
    const __nv_bfloat16* __restrict__ A, const float* __restrict__ B,
    __nv_bfloat16* __restrict__ C, int N, int K, int lda, size_t sA, size_t sB, size_t sC)
{
    __shared__ uint32_t As[16][PA];
    __shared__ uint32_t Bs[16][PB];
    const int tid = threadIdx.x;
    const int lane = tid & 31, wid = tid >> 5;
    const int wm = (wid & 1) * 64, wn = (wid >> 1) * 32;
    const int m0 = blockIdx.y * BM, n0 = blockIdx.x * BN;
    A += (size_t)blockIdx.z * sA;
    B += (size_t)blockIdx.z * sB;
    C += (size_t)blockIdx.z * sC;

    const int xM4 = (tid & 31) * 4, xP = tid >> 5;

    uint2 pa[4];
    float4 rb[4];
    pa[0] = *(const uint2*)(A + (size_t)(2 * xP) * lda + m0 + xM4);
    pa[1] = *(const uint2*)(A + (size_t)(2 * xP + 1) * lda + m0 + xM4);
    pa[2] = *(const uint2*)(A + (size_t)(2 * xP + 16) * lda + m0 + xM4);
    pa[3] = *(const uint2*)(A + (size_t)(2 * xP + 17) * lda + m0 + xM4);
    rb[0] = *(const float4*)&B[(size_t)(2 * xP) * N + n0 + xM4];
    rb[1] = *(const float4*)&B[(size_t)(2 * xP + 1) * N + n0 + xM4];
    rb[2] = *(const float4*)&B[(size_t)(2 * xP + 16) * N + n0 + xM4];
    rb[3] = *(const float4*)&B[(size_t)(2 * xP + 17) * N + n0 + xM4];

    float acc[4][4][4] = {};
    const int nIters = K / BKE;
    for (int it = 0; it < nIters; it++) {
        // interleave rows k, k+1 into (k,k+1) words per m
        *(uint4*)&As[xP][xM4] = make_uint4(
            prmt(pa[0].x, pa[1].x, 0x5410), prmt(pa[0].x, pa[1].x, 0x7632),
            prmt(pa[0].y, pa[1].y, 0x5410), prmt(pa[0].y, pa[1].y, 0x7632));
        *(uint4*)&As[xP + 8][xM4] = make_uint4(
            prmt(pa[2].x, pa[3].x, 0x5410), prmt(pa[2].x, pa[3].x, 0x7632),
            prmt(pa[2].y, pa[3].y, 0x5410), prmt(pa[2].y, pa[3].y, 0x7632));
        *(uint4*)&Bs[xP][xM4] = pk4(rb[0], rb[1]);
        *(uint4*)&Bs[xP + 8][xM4] = pk4(rb[2], rb[3]);
        __syncthreads();
        if (it + 1 < nIters) {
            int k0 = (it + 1) * BKE;
            pa[0] = *(const uint2*)(A + (size_t)(k0 + 2 * xP) * lda + m0 + xM4);
            pa[1] = *(const uint2*)(A + (size_t)(k0 + 2 * xP + 1) * lda + m0 + xM4);
            pa[2] = *(const uint2*)(A + (size_t)(k0 + 2 * xP + 16) * lda + m0 + xM4);
            pa[3] = *(const uint2*)(A + (size_t)(k0 + 2 * xP + 17) * lda + m0 + xM4);
            rb[0] = *(const float4*)&B[(size_t)(k0 + 2 * xP) * N + n0 + xM4];
            rb[1] = *(const float4*)&B[(size_t)(k0 + 2 * xP + 1) * N + n0 + xM4];
            rb[2] = *(const float4*)&B[(size_t)(k0 + 2 * xP + 16) * N + n0 + xM4];
            rb[3] = *(const float4*)&B[(size_t)(k0 + 2 * xP + 17) * N + n0 + xM4];
        }
        mma_compute(As, Bs, lane, wm, wn, acc);
        __syncthreads();
    }
    const int c4 = lane & 3, g8 = lane >> 2;
#pragma unroll
    for (int mi = 0; mi < 4; mi++)
#pragma unroll
        for (int ni = 0; ni < 4; ni++) {
            int row = m0 + wm + mi * 16 + g8;
            int col = n0 + wn + ni * 8 + 2 * c4;
            *(uint32_t*)&C[(size_t)row * N + col] = pk(acc[mi][ni][0], acc[mi][ni][1]);
            *(uint32_t*)&C[(size_t)(row + 8) * N + col] = pk(acc[mi][ni][2], acc[mi][ni][3]);
        }
}

// Step 8: r[b,n] += sum_m relu( [X1_bf16|X2_f32][m,:] @ Wr + br )[n]  (K=2D, N=D)
__global__ __launch_bounds__(256) void mm_concat_rs(
    const __nv_bfloat16* __restrict__ X1, const float* __restrict__ X2,
    const float* __restrict__ Wr, const float* __restrict__ br,
    float* __restrict__ r, int L)
{
    __shared__ uint32_t As[16][PA];
    __shared__ uint32_t Bs[16][PB];
    __shared__ float colsum[BN];
    const int tid = threadIdx.x;
    const int lane = tid & 31, wid = tid >> 5;
    const int wm = (wid & 1) * 64, wn = (wid >> 1) * 32;
    const int b = blockIdx.z;
    const int m0 = blockIdx.y * BM, n0 = blockIdx.x * BN;
    const __nv_bfloat16* A1 = X1 + (size_t)b * L * DD;
    const float* A2 = X2 + (size_t)b * L * DD;

    if (tid < BN) colsum[tid] = 0.0f;

    const int aM = tid >> 2, aK = (tid & 3) * 8, aW = (tid & 3) * 4;
    const int bN4 = (tid & 31) * 4, bP = tid >> 5;

    uint32_t wa[8];
    float4 rb[4];
    {   // first tile: k0 = 0 < DD -> bf16 source
        uint4 q0 = *(const uint4*)(A1 + (size_t)(m0 + aM) * DD + aK);
        uint4 q1 = *(const uint4*)(A1 + (size_t)(m0 + aM + 64) * DD + aK);
        wa[0] = q0.x; wa[1] = q0.y; wa[2] = q0.z; wa[3] = q0.w;
        wa[4] = q1.x; wa[5] = q1.y; wa[6] = q1.z; wa[7] = q1.w;
    }
    rb[0] = *(const float4*)&Wr[(size_t)(2 * bP) * DD + n0 + bN4];
    rb[1] = *(const float4*)&Wr[(size_t)(2 * bP + 1) * DD + n0 + bN4];
    rb[2] = *(const float4*)&Wr[(size_t)(2 * bP + 16) * DD + n0 + bN4];
    rb[3] = *(const float4*)&Wr[(size_t)(2 * bP + 17) * DD + n0 + bN4];

    float acc[4][4][4] = {};
    const int nIters = (2 * DD) / BKE;   // 16
    for (int it = 0; it < nIters; it++) {
        As[aW + 0][aM] = wa[0]; As[aW + 1][aM] = wa[1];
        As[aW + 2][aM] = wa[2]; As[aW + 3][aM] = wa[3];
        As[aW + 0][aM + 64] = wa[4]; As[aW + 1][aM + 64] = wa[5];
        As[aW + 2][aM + 64] = wa[6]; As[aW + 3][aM + 64] = wa[7];
        *(uint4*)&Bs[bP][bN4] = pk4(rb[0], rb[1]);
        *(uint4*)&Bs[bP + 8][bN4] = pk4(rb[2], rb[3]);
        __syncthreads();
        if (it + 1 < nIters) {
            int k0 = (it + 1) * BKE;
            if (k0 < DD) {
                uint4 q0 = *(const uint4*)(A1 + (size_t)(m0 + aM) * DD + k0 + aK);
                uint4 q1 = *(const uint4*)(A1 + (size_t)(m0 + aM + 64) * DD + k0 + aK);
                wa[0] = q0.x; wa[1] = q0.y; wa[2] = q0.z; wa[3] = q0.w;
                wa[4] = q1.x; wa[5] = q1.y; wa[6] = q1.z; wa[7] = q1.w;
            } else {
                int kk = k0 - DD;
                float4 f0 = *(const float4*)&A2[(size_t)(m0 + aM) * DD + kk + aK];
                float4 f1 = *(const float4*)&A2[(size_t)(m0 + aM) * DD + kk + aK + 4];
                float4 f2 = *(const float4*)&A2[(size_t)(m0 + aM + 64) * DD + kk + aK];
                float4 f3 = *(const float4*)&A2[(size_t)(m0 + aM + 64) * DD + kk + aK + 4];
                wa[0] = pk(f0.x, f0.y); wa[1] = pk(f0.z, f0.w);
                wa[2] = pk(f1.x, f1.y); wa[3] = pk(f1.z, f1.w);
                wa[4] = pk(f2.x, f2.y); wa[5] = pk(f2.z, f2.w);
                wa[6] = pk(f3.x, f3.y); wa[7] = pk(f3.z, f3.w);
            }
            rb[0] = *(const float4*)&Wr[(size_t)(k0 + 2 * bP) * DD + n0 + bN4];
            rb[1] = *(const float4*)&Wr[(size_t)(k0 + 2 * bP + 1) * DD + n0 + bN4];
            rb[2] = *(const float4*)&Wr[(size_t)(k0 + 2 * bP + 16) * DD + n0 + bN4];
            rb[3] = *(const float4*)&Wr[(size_t)(k0 + 2 * bP + 17) * DD + n0 + bN4];
        }
        mma_compute(As, Bs, lane, wm, wn, acc);
        __syncthreads();
    }
    const int c4 = lane & 3;
#pragma unroll
    for (int ni = 0; ni < 4; ni++) {
        int col = wn + ni * 8 + 2 * c4;
        float b0 = br[n0 + col], b1 = br[n0 + col + 1];
        float s0 = 0.f, s1 = 0.f;
#pragma unroll
        for (int mi = 0; mi < 4; mi++) {
            s0 += fmaxf(acc[mi][ni][0] + b0, 0.f) + fmaxf(acc[mi][ni][2] + b0, 0.f);
            s1 += fmaxf(acc[mi][ni][1] + b1, 0.f) + fmaxf(acc[mi][ni][3] + b1, 0.f);
        }
        atomicAdd(&colsum[col], s0);
        atomicAdd(&colsum[col + 1], s1);
    }
    __syncthreads();
    if (tid < BN) atomicAdd(&r[(size_t)b * DD + n0 + tid], colsum[tid]);
}

// ---------------- softmax kernels ----------------

// beta_bf16 = softmax over Lc (column-wise), masked. Reads align f32.
__global__ void beta_kernel(const float* __restrict__ align_, __nv_bfloat16* __restrict__ beta,
                            const int* __restrict__ cmask)
{
    const int b = blockIdx.y;
    const int e = blockIdx.x * 32 + threadIdx.x;
    const int tx = threadIdx.x, ty = threadIdx.y;
    const float* base = align_ + (size_t)b * LC * LE + e;
    __nv_bfloat16* outb = beta + (size_t)b * LC * LE + e;

    float vals[LC / 8];
    float mx = -INFINITY;
#pragma unroll
    for (int i = 0; i < LC / 8; i++) {
        int l = ty + i * 8;
        float v = base[(size_t)l * LE] + (1.0f - (float)cmask[b * LC + l]) * NEGV;
        vals[i] = v;
        mx = fmaxf(mx, v);
    }
    __shared__ float red[8][32];
    red[ty][tx] = mx;
    __syncthreads();
    if (ty == 0) {
        float m2 = red[0][tx];
#pragma unroll
        for (int i = 1; i < 8; i++) m2 = fmaxf(m2, red[i][tx]);
        red[0][tx] = m2;
    }
    __syncthreads();
    mx = red[0][tx];
    __syncthreads();

    float s = 0.0f;
#pragma unroll
    for (int i = 0; i < LC / 8; i++) {
        vals[i] = expf(vals[i] - mx);
        s += vals[i];
    }
    red[ty][tx] = s;
    __syncthreads();
    if (ty == 0) {
        float s2 = 0.0f;
#pragma unroll
        for (int i = 0; i < 8; i++) s2 += red[i][tx];
        red[0][tx] = s2;
    }
    __syncthreads();
    float inv = 1.0f / red[0][tx];
#pragma unroll
    for (int i = 0; i < LC / 8; i++) {
        int l = ty + i * 8;
        outb[(size_t)l * LE] = __float2bfloat16_rn(vals[i] * inv);
    }
}

// alpha_bf16 = softmax over Le (row-wise), masked. Reads align f32, writes alpha bf16.
__global__ void alpha_kernel(const float* __restrict__ align_, __nv_bfloat16* __restrict__ alpha,
                             const int* __restrict__ emask)
{
    const int b = blockIdx.y;
    const int l = blockIdx.x;
    const int t = threadIdx.x;
    const float* row = align_ + ((size_t)b * LC + l) * LE;
    __nv_bfloat16* arow = alpha + ((size_t)b * LC + l) * LE;

    float v[4];
    float mx = -INFINITY;
#pragma unroll
    for (int j = 0; j < 4; j++) {
        int e = t + j * 256;
        v[j] = row[e] + (1.0f - (float)emask[b * LE + e]) * NEGV;
        mx = fmaxf(mx, v[j]);
    }
    __shared__ float sm[256];
    sm[t] = mx;
    __syncthreads();
    for (int s = 128; s > 0; s >>= 1) {
        if (t < s) sm[t] = fmaxf(sm[t], sm[t + s]);
        __syncthreads();
    }
    mx = sm[0];
    __syncthreads();

    float sum = 0.0f;
#pragma unroll
    for (int j = 0; j < 4; j++) {
        v[j] = expf(v[j] - mx);
        sum += v[j];
    }
    sm[t] = sum;
    __syncthreads();
    for (int s = 128; s > 0; s >>= 1) {
        if (t < s) sm[t] += sm[t + s];
        __syncthreads();
    }
    float inv = 1.0f / sm[0];
#pragma unroll
    for (int j = 0; j < 4; j++) arow[t + j * 256] = __float2bfloat16_rn(v[j] * inv);
}

// ---------------- final head ----------------
__global__ void head_kernel(const float* __restrict__ r1, const float* __restrict__ r2,
                            const float* __restrict__ Wm, const float* __restrict__ bm,
                            const float* __restrict__ Wo, const float* __restrict__ bo,
                            float* __restrict__ out)
{
    const int b = blockIdx.x;
    const int t = threadIdx.x;
    __shared__ float mv[4 * DD];
    __shared__ float outacc[3];
    if (t < DD) {
        float a = r1[(size_t)b * DD + t];
        float c = r2[(size_t)b * DD + t];
        mv[t] = a;
        mv[DD + t] = c;
        mv[2 * DD + t] = a * c;
        mv[3 * DD + t] = a - c;
    }
    if (t < 3) outacc[t] = 0.0f;
    __syncthreads();

    float acc = bm[t];
#pragma unroll 8
    for (int k = 0; k < 4 * DD; k++) acc = fmaf(mv[k], Wm[(size_t)k * MM + t], acc);
    float h = fmaxf(acc, 0.0f);

#pragma unroll
    for (int i = 0; i < 3; i++) atomicAdd(&outacc[i], h * Wo[(size_t)t * 3 + i]);
    __syncthreads();
    if (t < 3) out[(size_t)b * 3 + t] = outacc[t] + bo[t];
}

// ---------------- launch ----------------
extern "C" void kernel_launch(void* const* d_in, const int* in_sizes, int n_in,
                              void* d_out, int out_size)
{
    const float* criteria = (const float*)d_in[0];
    const float* ehr      = (const float*)d_in[1];
    const int*   cmask    = (const int*)d_in[2];
    const int*   emask    = (const int*)d_in[3];
    const float* Wa       = (const float*)d_in[4];
    const float* ba       = (const float*)d_in[5];
    const float* Wr       = (const float*)d_in[6];
    const float* br       = (const float*)d_in[7];
    const float* Wm       = (const float*)d_in[8];
    const float* bm       = (const float*)d_in[9];
    const float* Wo       = (const float*)d_in[10];
    const float* bo       = (const float*)d_in[11];
    float* out = (float*)d_out;

    float* base;
    cudaGetSymbolAddress((void**)&base, g_scratch);
    __nv_bfloat16* p_c     = (__nv_bfloat16*)(base + OFF_CB);
    __nv_bfloat16* p_e     = (__nv_bfloat16*)(base + OFF_EB);
    float*         p_align = base + OFF_ALIGN;
    __nv_bfloat16* p_beta  = (__nv_bfloat16*)(base + OFF_EB);  // alias: e dead after step 3
    __nv_bfloat16* p_alpha = (__nv_bfloat16*)(base + OFF_ALPHA);
    __nv_bfloat16* p_attc  = (__nv_bfloat16*)(base + OFF_CB);  // alias: c dead after step 3
    __nv_bfloat16* p_atte  = (__nv_bfloat16*)(base + OFF_ATTE);
    float*         p_r1    = base + OFF_R1;
    float*         p_r2    = base + OFF_R2;

    // 1) c = relu(criteria @ Wa + ba) -> bf16
    mm_proj<<<dim3(DD / BN, (BB * LC) / BM), 256>>>(criteria, Wa, ba, p_c, DD, DD);
    // 2) e = relu(ehr @ Wa + ba) -> bf16
    mm_proj<<<dim3(DD / BN, (BB * LE) / BM), 256>>>(ehr, Wa, ba, p_e, DD, DD);
    // 3) align = c @ e^T -> fp32
    mm_align<<<dim3(LE / BN, LC / BM, BB), 256>>>(
        p_c, p_e, p_align, LE, DD,
        (size_t)LC * DD, (size_t)LE * DD, (size_t)LC * LE);
    // 4) beta (softmax over Lc) -> bf16, aliases e
    beta_kernel<<<dim3(LE / 32, BB), dim3(32, 8)>>>(p_align, p_beta, cmask);
    // 5) alpha (softmax over Le) -> bf16
    alpha_kernel<<<dim3(LC, BB), 256>>>(p_align, p_alpha, emask);
    // 6) att_c = alpha @ ehr -> bf16, aliases c
    mm_attc<<<dim3(DD / BN, LC / BM, BB), 256>>>(
        p_alpha, ehr, p_attc, DD, LE,
        (size_t)LC * LE, (size_t)LE * DD, (size_t)LC * DD);
    // 7) att_e = beta^T @ criteria -> bf16
    mm_atte<<<dim3(DD / BN, LE / BM, BB), 256>>>(
        p_beta, criteria, p_atte, DD, LC, LE,
        (size_t)LC * LE, (size_t)LC * DD, (size_t)LE * DD);
    // 8) r1, r2 (fused concat GEMM + relu + row-sum)
    cudaMemsetAsync(p_r1, 0, (size_t)2 * BB * DD * sizeof(float));
    mm_concat_rs<<<dim3(DD / BN, LC / BM, BB), 256>>>(p_attc, criteria, Wr, br, p_r1, LC);
    mm_concat_rs<<<dim3(DD / BN, LE / BM, BB), 256>>>(p_atte, ehr, Wr, br, p_r2, LE);
    // 9) head
    head_kernel<<<BB, MM>>>(p_r1, p_r2, Wm, bm, Wo, bo, out);
}